// round 1
// baseline (speedup 1.0000x reference)
#include <cuda_runtime.h>
#include <math.h>

// Problem constants
#define B_   16
#define C_   256
#define HH_  64
#define WW_  64
#define N_   4096      // HH*WW
#define K_   16
#define H_   4
#define U_   4
#define R_   23
#define DV_  64
#define EPS_ 1e-3f

// Scratch (device globals; no allocation allowed)
__device__ float g_wfold[384 * 256];
__device__ float g_bias[384];
__device__ float g_proj[(size_t)B_ * 384 * N_];            // 100.7 MB: rows 0-63 q, 64-127 k, 128-383 v
__device__ float g_LcPart[(size_t)B_ * 32 * 1024];         // partials (u*8+s)
__device__ float g_Lc[B_ * K_ * DV_];                      // [b][k][dv]
__device__ float g_Lp[(size_t)B_ * K_ * DV_ * N_];         // 268 MB

// ---------------------------------------------------------------------------
// K1: fold BN into projection weights. o<64: q, o<128: k (no BN), o<384: v
// ---------------------------------------------------------------------------
__global__ void fold_kernel(const float* __restrict__ w_q, const float* __restrict__ w_k,
                            const float* __restrict__ w_v,
                            const float* __restrict__ gq, const float* __restrict__ bq,
                            const float* __restrict__ mq, const float* __restrict__ vq,
                            const float* __restrict__ gv, const float* __restrict__ bv,
                            const float* __restrict__ mv, const float* __restrict__ vvar) {
    int o = blockIdx.x * blockDim.x + threadIdx.x;
    if (o >= 384) return;
    if (o < 64) {
        float inv = gq[o] * rsqrtf(vq[o] + EPS_);
        g_bias[o] = bq[o] - mq[o] * inv;
        for (int c = 0; c < 256; c++) g_wfold[o * 256 + c] = w_q[o * 256 + c] * inv;
    } else if (o < 128) {
        int i = o - 64;
        g_bias[o] = 0.f;
        for (int c = 0; c < 256; c++) g_wfold[o * 256 + c] = w_k[i * 256 + c];
    } else {
        int i = o - 128;
        float inv = gv[i] * rsqrtf(vvar[i] + EPS_);
        g_bias[o] = bv[i] - mv[i] * inv;
        for (int c = 0; c < 256; c++) g_wfold[o * 256 + c] = w_v[i * 256 + c] * inv;
    }
}

// ---------------------------------------------------------------------------
// K2: projection GEMM.  proj[b, o, n] = wfold[o,:] @ x[b,:,n] + bias[o]
// Block tile: 64(M) x 128(N), BK=16, 256 threads, 4x8 per thread.
// ---------------------------------------------------------------------------
__global__ __launch_bounds__(256) void proj_gemm_kernel(const float* __restrict__ x) {
    __shared__ float As[16][64];
    __shared__ float Bs[16][128];
    const int b  = blockIdx.z;
    const int m0 = blockIdx.y * 64;
    const int n0 = blockIdx.x * 128;
    const int tid = threadIdx.x;
    const int tx = tid & 15, ty = tid >> 4;
    const float* xb = x + (size_t)b * C_ * N_ + n0;

    float acc[4][8];
#pragma unroll
    for (int j = 0; j < 4; j++)
#pragma unroll
        for (int i = 0; i < 8; i++) acc[j][i] = 0.f;

    for (int k0 = 0; k0 < 256; k0 += 16) {
#pragma unroll
        for (int l = 0; l < 4; l++) {
            int e = tid + l * 256;
            int m = e & 63, kk = e >> 6;
            As[kk][m] = g_wfold[(m0 + m) * 256 + k0 + kk];
        }
#pragma unroll
        for (int l = 0; l < 8; l++) {
            int e = tid + l * 256;
            int kk = e >> 7, n = e & 127;
            Bs[kk][n] = xb[(size_t)(k0 + kk) * N_ + n];
        }
        __syncthreads();
#pragma unroll
        for (int kk = 0; kk < 16; kk++) {
            float4 a4 = *(const float4*)&As[kk][ty * 4];
            float4 b0 = *(const float4*)&Bs[kk][tx * 8];
            float4 b1 = *(const float4*)&Bs[kk][tx * 8 + 4];
            float av[4] = {a4.x, a4.y, a4.z, a4.w};
            float bv2[8] = {b0.x, b0.y, b0.z, b0.w, b1.x, b1.y, b1.z, b1.w};
#pragma unroll
            for (int j = 0; j < 4; j++)
#pragma unroll
                for (int i = 0; i < 8; i++) acc[j][i] = fmaf(av[j], bv2[i], acc[j][i]);
        }
        __syncthreads();
    }
#pragma unroll
    for (int j = 0; j < 4; j++) {
        int m = m0 + ty * 4 + j;
        float bi = g_bias[m];
        float* dst = g_proj + ((size_t)b * 384 + m) * N_ + n0 + tx * 8;
#pragma unroll
        for (int i = 0; i < 8; i++) dst[i] = acc[j][i] + bi;
    }
}

// ---------------------------------------------------------------------------
// K3: softmax over positions for k rows (proj rows 64..127), in place.
// One block (256 thr) per row of 4096.
// ---------------------------------------------------------------------------
__global__ __launch_bounds__(256) void softmax_kernel() {
    __shared__ float red[8];
    const int row = blockIdx.x;
    const int b = row >> 6, r = row & 63;
    float* p = g_proj + ((size_t)b * 384 + 64 + r) * N_;
    const int tid = threadIdx.x, lane = tid & 31, wid = tid >> 5;

    float v[16];
    float mx = -3.4e38f;
#pragma unroll
    for (int l = 0; l < 16; l++) {
        v[l] = p[tid + l * 256];
        mx = fmaxf(mx, v[l]);
    }
#pragma unroll
    for (int o = 16; o; o >>= 1) mx = fmaxf(mx, __shfl_xor_sync(0xffffffffu, mx, o));
    if (!lane) red[wid] = mx;
    __syncthreads();
    mx = red[0];
#pragma unroll
    for (int w = 1; w < 8; w++) mx = fmaxf(mx, red[w]);

    float s = 0.f;
#pragma unroll
    for (int l = 0; l < 16; l++) {
        v[l] = expf(v[l] - mx);
        s += v[l];
    }
#pragma unroll
    for (int o = 16; o; o >>= 1) s += __shfl_xor_sync(0xffffffffu, s, o);
    __syncthreads();
    if (!lane) red[wid] = s;
    __syncthreads();
    s = 0.f;
#pragma unroll
    for (int w = 0; w < 8; w++) s += red[w];
    float inv = 1.0f / s;
#pragma unroll
    for (int l = 0; l < 16; l++) p[tid + l * 256] = v[l] * inv;
}

// ---------------------------------------------------------------------------
// K4a: Lc partials.  block=(s,u,b): partial over m-slice of 512 for one u.
// Deterministic (no atomics): writes to g_LcPart.
// ---------------------------------------------------------------------------
__global__ __launch_bounds__(256) void lc_partial_kernel() {
    __shared__ float ks[16][64];
    __shared__ float vsm[64][65];
    const int s = blockIdx.x, u = blockIdx.y, b = blockIdx.z;
    const int tid = threadIdx.x;
    const int kk = tid >> 4, vg = tid & 15;
    float acc[4] = {0.f, 0.f, 0.f, 0.f};
    const float* kbase = g_proj + ((size_t)b * 384 + 64 + u * 16) * N_;
    const float* vbase = g_proj + ((size_t)b * 384 + 128 + u * 64) * N_;
    const int m0b = s * 512;

    for (int mc = 0; mc < 512; mc += 64) {
        const int m0 = m0b + mc;
#pragma unroll
        for (int l = 0; l < 4; l++) {
            int e = tid + l * 256;
            ks[e >> 6][e & 63] = kbase[(size_t)(e >> 6) * N_ + m0 + (e & 63)];
        }
#pragma unroll
        for (int l = 0; l < 16; l++) {
            int e = tid + l * 256;
            vsm[e >> 6][e & 63] = vbase[(size_t)(e >> 6) * N_ + m0 + (e & 63)];
        }
        __syncthreads();
#pragma unroll 8
        for (int m = 0; m < 64; m++) {
            float kv = ks[kk][m];
#pragma unroll
            for (int j = 0; j < 4; j++) acc[j] = fmaf(kv, vsm[vg * 4 + j][m], acc[j]);
        }
        __syncthreads();
    }
    float* dst = g_LcPart + (((size_t)b * 4 + u) * 8 + s) * 1024 + kk * 64 + vg * 4;
#pragma unroll
    for (int j = 0; j < 4; j++) dst[j] = acc[j];
}

// K4b: reduce 32 partials -> Lc (deterministic order)
__global__ void lc_reduce_kernel() {
    const int b = blockIdx.x;
    const int t = threadIdx.x;  // 1024
    float s = 0.f;
#pragma unroll
    for (int p = 0; p < 32; p++) s += g_LcPart[((size_t)b * 32 + p) * 1024 + t];
    g_Lc[b * 1024 + t] = s;
}

// ---------------------------------------------------------------------------
// K5: position conv (the heavy one).
// Lp[b,k,dv,n] = b_pos[k] + sum_{u,dy,dx} w_pos[k,u,dy,dx] * v[b,u,dv, y+dy-11, x+dx-11]
// Block: one (b, dv, 32x32 quadrant). 128 threads. Thread: 16 px x 8 k.
// smem: v halo 54x54 (one u at a time) + weights [16][529] for that u.
// ---------------------------------------------------------------------------
__global__ __launch_bounds__(128) void conv_kernel(const float* __restrict__ w_pos,
                                                   const float* __restrict__ b_pos) {
    __shared__ float vs[54 * 54];   // 11.66 KB
    __shared__ float ws[16 * 529];  // 33.86 KB
    const int quad = blockIdx.x;           // 0..3
    const int dv   = blockIdx.y;           // 0..63
    const int b    = blockIdx.z;           // 0..15
    const int Y0 = (quad >> 1) * 32;
    const int X0 = (quad & 1) * 32;
    const int tid = threadIdx.x;
    const int kh  = tid & 1;               // k half
    const int g   = tid >> 1;              // 0..63
    const int col = g & 31;
    const int rb  = (g >> 5) * 16;         // 0 or 16

    float acc[16][8];
#pragma unroll
    for (int i = 0; i < 16; i++)
#pragma unroll
        for (int j = 0; j < 8; j++) acc[i][j] = 0.f;

    for (int u = 0; u < 4; u++) {
        __syncthreads();
        const float* vimg = g_proj + ((size_t)b * 384 + 128 + u * 64 + dv) * N_;
        for (int e = tid; e < 54 * 54; e += 128) {
            int r = e / 54, c = e - r * 54;
            int y = Y0 + r - 11, x = X0 + c - 11;
            float val = 0.f;
            if (y >= 0 && y < 64 && x >= 0 && x < 64) val = vimg[y * 64 + x];
            vs[e] = val;
        }
        for (int e = tid; e < 16 * 529; e += 128) {
            int kk = e / 529, tap = e - kk * 529;
            ws[e] = w_pos[kk * (4 * 529) + u * 529 + tap];
        }
        __syncthreads();

        const float* wbase = ws + (kh * 8) * 529;
#pragma unroll 1
        for (int dy = 0; dy < 23; dy++) {
            const float* vr = vs + (rb + dy) * 54 + col;
            const float* wr = wbase + dy * 23;
#pragma unroll 1
            for (int dx = 0; dx < 23; dx++) {
                float wv[8];
#pragma unroll
                for (int j = 0; j < 8; j++) wv[j] = wr[j * 529 + dx];
#pragma unroll
                for (int i = 0; i < 16; i++) {
                    float vv = vr[i * 54 + dx];
#pragma unroll
                    for (int j = 0; j < 8; j++) acc[i][j] = fmaf(vv, wv[j], acc[i][j]);
                }
            }
        }
    }
    // epilogue: Lp[b][k][dv][n] = acc + b_pos[k]
#pragma unroll
    for (int j = 0; j < 8; j++) {
        const int kk = kh * 8 + j;
        const float bp = b_pos[kk];
        float* dst = g_Lp + (((size_t)b * 16 + kk) * 64 + dv) * N_;
#pragma unroll
        for (int i = 0; i < 16; i++) {
            int n = (Y0 + rb + i) * 64 + X0 + col;
            dst[n] = acc[i][j] + bp;
        }
    }
}

// ---------------------------------------------------------------------------
// K6: final combine.
// out[b, h*64+dv, n] = sum_k q[b,h,k,n] * (Lc[b,k,dv] + Lp[b,k,dv,n])
// Block: (ntile of 128, b). 128 threads, one px each. Loop dv.
// ---------------------------------------------------------------------------
__global__ __launch_bounds__(128) void final_kernel(float* __restrict__ out) {
    __shared__ float qs[64][128];   // 32 KB
    __shared__ float lps[16][128];  // 8 KB
    __shared__ float lcs[16][64];   // 4 KB
    const int n0 = blockIdx.x * 128;
    const int b  = blockIdx.y;
    const int tid = threadIdx.x;

    const float* qbase = g_proj + (size_t)b * 384 * N_ + n0;
    for (int l = 0; l < 64; l++) {
        int e = tid + l * 128;
        qs[e >> 7][e & 127] = qbase[(size_t)(e >> 7) * N_ + (e & 127)];
    }
#pragma unroll
    for (int l = 0; l < 8; l++) {
        int e = tid + l * 128;
        lcs[e >> 6][e & 63] = g_Lc[b * 1024 + e];
    }

    for (int dv = 0; dv < 64; dv++) {
        __syncthreads();
#pragma unroll
        for (int l = 0; l < 16; l++) {
            int e = tid + l * 128;
            int k = e >> 7, n = e & 127;
            lps[k][n] = g_Lp[(((size_t)b * 16 + k) * 64 + dv) * N_ + n0 + n];
        }
        __syncthreads();
        const int px = tid;
#pragma unroll
        for (int h = 0; h < 4; h++) {
            float y = 0.f;
#pragma unroll
            for (int k = 0; k < 16; k++)
                y = fmaf(qs[h * 16 + k][px], lcs[k][dv] + lps[k][px], y);
            out[((size_t)b * 256 + h * 64 + dv) * N_ + n0 + px] = y;
        }
    }
}

// ---------------------------------------------------------------------------
extern "C" void kernel_launch(void* const* d_in, const int* in_sizes, int n_in,
                              void* d_out, int out_size) {
    const float* x     = (const float*)d_in[0];
    const float* w_q   = (const float*)d_in[1];
    const float* w_k   = (const float*)d_in[2];
    const float* w_v   = (const float*)d_in[3];
    const float* gq    = (const float*)d_in[4];
    const float* bq    = (const float*)d_in[5];
    const float* mq    = (const float*)d_in[6];
    const float* vq    = (const float*)d_in[7];
    const float* gv    = (const float*)d_in[8];
    const float* bv    = (const float*)d_in[9];
    const float* mv    = (const float*)d_in[10];
    const float* vvar  = (const float*)d_in[11];
    const float* w_pos = (const float*)d_in[12];
    const float* b_pos = (const float*)d_in[13];
    float* out = (float*)d_out;

    fold_kernel<<<2, 256>>>(w_q, w_k, w_v, gq, bq, mq, vq, gv, bv, mv, vvar);
    proj_gemm_kernel<<<dim3(32, 6, 16), 256>>>(x);
    softmax_kernel<<<1024, 256>>>();
    lc_partial_kernel<<<dim3(8, 4, 16), 256>>>();
    lc_reduce_kernel<<<16, 1024>>>();
    conv_kernel<<<dim3(4, 64, 16), 128>>>(w_pos, b_pos);
    final_kernel<<<dim3(32, 16), 128>>>(out);
}

// round 2
// speedup vs baseline: 1.0008x; 1.0008x over previous
#include <cuda_runtime.h>
#include <math.h>

// Problem constants
#define B_   16
#define C_   256
#define HH_  64
#define WW_  64
#define N_   4096      // HH*WW
#define K_   16
#define H_   4
#define U_   4
#define R_   23
#define DV_  64
#define EPS_ 1e-3f

// Scratch (device globals; no allocation allowed)
__device__ float g_wfold[384 * 256];
__device__ float g_bias[384];
__device__ float g_proj[(size_t)B_ * 384 * N_];            // 100.7 MB: rows 0-63 q, 64-127 k, 128-383 v
__device__ float g_LcPart[(size_t)B_ * 32 * 1024];         // partials (u*8+s)
__device__ float g_Lc[B_ * K_ * DV_];                      // [b][k][dv]
__device__ float g_Lp[(size_t)B_ * K_ * DV_ * N_];         // 268 MB

// ---------------------------------------------------------------------------
// K1: fold BN into projection weights. o<64: q, o<128: k (no BN), o<384: v
// ---------------------------------------------------------------------------
__global__ void fold_kernel(const float* __restrict__ w_q, const float* __restrict__ w_k,
                            const float* __restrict__ w_v,
                            const float* __restrict__ gq, const float* __restrict__ bq,
                            const float* __restrict__ mq, const float* __restrict__ vq,
                            const float* __restrict__ gv, const float* __restrict__ bv,
                            const float* __restrict__ mv, const float* __restrict__ vvar) {
    int o = blockIdx.x * blockDim.x + threadIdx.x;
    if (o >= 384) return;
    if (o < 64) {
        float inv = gq[o] * rsqrtf(vq[o] + EPS_);
        g_bias[o] = bq[o] - mq[o] * inv;
        for (int c = 0; c < 256; c++) g_wfold[o * 256 + c] = w_q[o * 256 + c] * inv;
    } else if (o < 128) {
        int i = o - 64;
        g_bias[o] = 0.f;
        for (int c = 0; c < 256; c++) g_wfold[o * 256 + c] = w_k[i * 256 + c];
    } else {
        int i = o - 128;
        float inv = gv[i] * rsqrtf(vvar[i] + EPS_);
        g_bias[o] = bv[i] - mv[i] * inv;
        for (int c = 0; c < 256; c++) g_wfold[o * 256 + c] = w_v[i * 256 + c] * inv;
    }
}

// ---------------------------------------------------------------------------
// K2: projection GEMM.  proj[b, o, n] = wfold[o,:] @ x[b,:,n] + bias[o]
// Block tile: 64(M) x 128(N), BK=16, 256 threads, 4x8 per thread.
// ---------------------------------------------------------------------------
__global__ __launch_bounds__(256) void proj_gemm_kernel(const float* __restrict__ x) {
    __shared__ float As[16][64];
    __shared__ float Bs[16][128];
    const int b  = blockIdx.z;
    const int m0 = blockIdx.y * 64;
    const int n0 = blockIdx.x * 128;
    const int tid = threadIdx.x;
    const int tx = tid & 15, ty = tid >> 4;
    const float* xb = x + (size_t)b * C_ * N_ + n0;

    float acc[4][8];
#pragma unroll
    for (int j = 0; j < 4; j++)
#pragma unroll
        for (int i = 0; i < 8; i++) acc[j][i] = 0.f;

    for (int k0 = 0; k0 < 256; k0 += 16) {
#pragma unroll
        for (int l = 0; l < 4; l++) {
            int e = tid + l * 256;
            int m = e & 63, kk = e >> 6;
            As[kk][m] = g_wfold[(m0 + m) * 256 + k0 + kk];
        }
#pragma unroll
        for (int l = 0; l < 8; l++) {
            int e = tid + l * 256;
            int kk = e >> 7, n = e & 127;
            Bs[kk][n] = xb[(size_t)(k0 + kk) * N_ + n];
        }
        __syncthreads();
#pragma unroll
        for (int kk = 0; kk < 16; kk++) {
            float4 a4 = *(const float4*)&As[kk][ty * 4];
            float4 b0 = *(const float4*)&Bs[kk][tx * 8];
            float4 b1 = *(const float4*)&Bs[kk][tx * 8 + 4];
            float av[4] = {a4.x, a4.y, a4.z, a4.w};
            float bv2[8] = {b0.x, b0.y, b0.z, b0.w, b1.x, b1.y, b1.z, b1.w};
#pragma unroll
            for (int j = 0; j < 4; j++)
#pragma unroll
                for (int i = 0; i < 8; i++) acc[j][i] = fmaf(av[j], bv2[i], acc[j][i]);
        }
        __syncthreads();
    }
#pragma unroll
    for (int j = 0; j < 4; j++) {
        int m = m0 + ty * 4 + j;
        float bi = g_bias[m];
        float* dst = g_proj + ((size_t)b * 384 + m) * N_ + n0 + tx * 8;
#pragma unroll
        for (int i = 0; i < 8; i++) dst[i] = acc[j][i] + bi;
    }
}

// ---------------------------------------------------------------------------
// K3: softmax over positions for k rows (proj rows 64..127), in place.
// One block (256 thr) per row of 4096.
// ---------------------------------------------------------------------------
__global__ __launch_bounds__(256) void softmax_kernel() {
    __shared__ float red[8];
    const int row = blockIdx.x;
    const int b = row >> 6, r = row & 63;
    float* p = g_proj + ((size_t)b * 384 + 64 + r) * N_;
    const int tid = threadIdx.x, lane = tid & 31, wid = tid >> 5;

    float v[16];
    float mx = -3.4e38f;
#pragma unroll
    for (int l = 0; l < 16; l++) {
        v[l] = p[tid + l * 256];
        mx = fmaxf(mx, v[l]);
    }
#pragma unroll
    for (int o = 16; o; o >>= 1) mx = fmaxf(mx, __shfl_xor_sync(0xffffffffu, mx, o));
    if (!lane) red[wid] = mx;
    __syncthreads();
    mx = red[0];
#pragma unroll
    for (int w = 1; w < 8; w++) mx = fmaxf(mx, red[w]);

    float s = 0.f;
#pragma unroll
    for (int l = 0; l < 16; l++) {
        v[l] = expf(v[l] - mx);
        s += v[l];
    }
#pragma unroll
    for (int o = 16; o; o >>= 1) s += __shfl_xor_sync(0xffffffffu, s, o);
    __syncthreads();
    if (!lane) red[wid] = s;
    __syncthreads();
    s = 0.f;
#pragma unroll
    for (int w = 0; w < 8; w++) s += red[w];
    float inv = 1.0f / s;
#pragma unroll
    for (int l = 0; l < 16; l++) p[tid + l * 256] = v[l] * inv;
}

// ---------------------------------------------------------------------------
// K4a: Lc partials.  block=(s,u,b): partial over m-slice of 512 for one u.
// Deterministic (no atomics): writes to g_LcPart.
// ---------------------------------------------------------------------------
__global__ __launch_bounds__(256) void lc_partial_kernel() {
    __shared__ float ks[16][64];
    __shared__ float vsm[64][65];
    const int s = blockIdx.x, u = blockIdx.y, b = blockIdx.z;
    const int tid = threadIdx.x;
    const int kk = tid >> 4, vg = tid & 15;
    float acc[4] = {0.f, 0.f, 0.f, 0.f};
    const float* kbase = g_proj + ((size_t)b * 384 + 64 + u * 16) * N_;
    const float* vbase = g_proj + ((size_t)b * 384 + 128 + u * 64) * N_;
    const int m0b = s * 512;

    for (int mc = 0; mc < 512; mc += 64) {
        const int m0 = m0b + mc;
#pragma unroll
        for (int l = 0; l < 4; l++) {
            int e = tid + l * 256;
            ks[e >> 6][e & 63] = kbase[(size_t)(e >> 6) * N_ + m0 + (e & 63)];
        }
#pragma unroll
        for (int l = 0; l < 16; l++) {
            int e = tid + l * 256;
            vsm[e >> 6][e & 63] = vbase[(size_t)(e >> 6) * N_ + m0 + (e & 63)];
        }
        __syncthreads();
#pragma unroll 8
        for (int m = 0; m < 64; m++) {
            float kv = ks[kk][m];
#pragma unroll
            for (int j = 0; j < 4; j++) acc[j] = fmaf(kv, vsm[vg * 4 + j][m], acc[j]);
        }
        __syncthreads();
    }
    float* dst = g_LcPart + (((size_t)b * 4 + u) * 8 + s) * 1024 + kk * 64 + vg * 4;
#pragma unroll
    for (int j = 0; j < 4; j++) dst[j] = acc[j];
}

// K4b: reduce 32 partials -> Lc (deterministic order)
__global__ void lc_reduce_kernel() {
    const int b = blockIdx.x;
    const int t = threadIdx.x;  // 1024
    float s = 0.f;
#pragma unroll
    for (int p = 0; p < 32; p++) s += g_LcPart[((size_t)b * 32 + p) * 1024 + t];
    g_Lc[b * 1024 + t] = s;
}

// ---------------------------------------------------------------------------
// K5: position conv (the heavy one).
// Lp[b,k,dv,n] = b_pos[k] + sum_{u,dy,dx} w_pos[k,u,dy,dx] * v[b,u,dv, y+dy-11, x+dx-11]
// Block: one (b, dv, 32x32 quadrant). 128 threads. Thread: 16 px x 8 k.
// smem: v halo 54x54 (one u at a time) + weights [16][529] for that u.
// ---------------------------------------------------------------------------
__global__ __launch_bounds__(128) void conv_kernel(const float* __restrict__ w_pos,
                                                   const float* __restrict__ b_pos) {
    __shared__ float vs[54 * 54];   // 11.66 KB
    __shared__ float ws[16 * 529];  // 33.86 KB
    const int quad = blockIdx.x;           // 0..3
    const int dv   = blockIdx.y;           // 0..63
    const int b    = blockIdx.z;           // 0..15
    const int Y0 = (quad >> 1) * 32;
    const int X0 = (quad & 1) * 32;
    const int tid = threadIdx.x;
    const int kh  = tid & 1;               // k half
    const int g   = tid >> 1;              // 0..63
    const int col = g & 31;
    const int rb  = (g >> 5) * 16;         // 0 or 16

    float acc[16][8];
#pragma unroll
    for (int i = 0; i < 16; i++)
#pragma unroll
        for (int j = 0; j < 8; j++) acc[i][j] = 0.f;

    for (int u = 0; u < 4; u++) {
        __syncthreads();
        const float* vimg = g_proj + ((size_t)b * 384 + 128 + u * 64 + dv) * N_;
        for (int e = tid; e < 54 * 54; e += 128) {
            int r = e / 54, c = e - r * 54;
            int y = Y0 + r - 11, x = X0 + c - 11;
            float val = 0.f;
            if (y >= 0 && y < 64 && x >= 0 && x < 64) val = vimg[y * 64 + x];
            vs[e] = val;
        }
        for (int e = tid; e < 16 * 529; e += 128) {
            int kk = e / 529, tap = e - kk * 529;
            ws[e] = w_pos[kk * (4 * 529) + u * 529 + tap];
        }
        __syncthreads();

        const float* wbase = ws + (kh * 8) * 529;
#pragma unroll 1
        for (int dy = 0; dy < 23; dy++) {
            const float* vr = vs + (rb + dy) * 54 + col;
            const float* wr = wbase + dy * 23;
#pragma unroll 1
            for (int dx = 0; dx < 23; dx++) {
                float wv[8];
#pragma unroll
                for (int j = 0; j < 8; j++) wv[j] = wr[j * 529 + dx];
#pragma unroll
                for (int i = 0; i < 16; i++) {
                    float vv = vr[i * 54 + dx];
#pragma unroll
                    for (int j = 0; j < 8; j++) acc[i][j] = fmaf(vv, wv[j], acc[i][j]);
                }
            }
        }
    }
    // epilogue: Lp[b][k][dv][n] = acc + b_pos[k]
#pragma unroll
    for (int j = 0; j < 8; j++) {
        const int kk = kh * 8 + j;
        const float bp = b_pos[kk];
        float* dst = g_Lp + (((size_t)b * 16 + kk) * 64 + dv) * N_;
#pragma unroll
        for (int i = 0; i < 16; i++) {
            int n = (Y0 + rb + i) * 64 + X0 + col;
            dst[n] = acc[i][j] + bp;
        }
    }
}

// ---------------------------------------------------------------------------
// K6: final combine.
// out[b, h*64+dv, n] = sum_k q[b,h,k,n] * (Lc[b,k,dv] + Lp[b,k,dv,n])
// Block: (ntile of 128, b). 128 threads, one px each. Loop dv.
// ---------------------------------------------------------------------------
__global__ __launch_bounds__(128) void final_kernel(float* __restrict__ out) {
    __shared__ float qs[64][128];   // 32 KB
    __shared__ float lps[16][128];  // 8 KB
    __shared__ float lcs[16][64];   // 4 KB
    const int n0 = blockIdx.x * 128;
    const int b  = blockIdx.y;
    const int tid = threadIdx.x;

    const float* qbase = g_proj + (size_t)b * 384 * N_ + n0;
    for (int l = 0; l < 64; l++) {
        int e = tid + l * 128;
        qs[e >> 7][e & 127] = qbase[(size_t)(e >> 7) * N_ + (e & 127)];
    }
#pragma unroll
    for (int l = 0; l < 8; l++) {
        int e = tid + l * 128;
        lcs[e >> 6][e & 63] = g_Lc[b * 1024 + e];
    }

    for (int dv = 0; dv < 64; dv++) {
        __syncthreads();
#pragma unroll
        for (int l = 0; l < 16; l++) {
            int e = tid + l * 128;
            int k = e >> 7, n = e & 127;
            lps[k][n] = g_Lp[(((size_t)b * 16 + k) * 64 + dv) * N_ + n0 + n];
        }
        __syncthreads();
        const int px = tid;
#pragma unroll
        for (int h = 0; h < 4; h++) {
            float y = 0.f;
#pragma unroll
            for (int k = 0; k < 16; k++)
                y = fmaf(qs[h * 16 + k][px], lcs[k][dv] + lps[k][px], y);
            out[((size_t)b * 256 + h * 64 + dv) * N_ + n0 + px] = y;
        }
    }
}

// ---------------------------------------------------------------------------
extern "C" void kernel_launch(void* const* d_in, const int* in_sizes, int n_in,
                              void* d_out, int out_size) {
    const float* x     = (const float*)d_in[0];
    const float* w_q   = (const float*)d_in[1];
    const float* w_k   = (const float*)d_in[2];
    const float* w_v   = (const float*)d_in[3];
    const float* gq    = (const float*)d_in[4];
    const float* bq    = (const float*)d_in[5];
    const float* mq    = (const float*)d_in[6];
    const float* vq    = (const float*)d_in[7];
    const float* gv    = (const float*)d_in[8];
    const float* bv    = (const float*)d_in[9];
    const float* mv    = (const float*)d_in[10];
    const float* vvar  = (const float*)d_in[11];
    const float* w_pos = (const float*)d_in[12];
    const float* b_pos = (const float*)d_in[13];
    float* out = (float*)d_out;

    fold_kernel<<<2, 256>>>(w_q, w_k, w_v, gq, bq, mq, vq, gv, bv, mv, vvar);
    proj_gemm_kernel<<<dim3(32, 6, 16), 256>>>(x);
    softmax_kernel<<<1024, 256>>>();
    lc_partial_kernel<<<dim3(8, 4, 16), 256>>>();
    lc_reduce_kernel<<<16, 1024>>>();
    conv_kernel<<<dim3(4, 64, 16), 128>>>(w_pos, b_pos);
    final_kernel<<<dim3(32, 16), 128>>>(out);
}

// round 3
// speedup vs baseline: 1.1032x; 1.1023x over previous
#include <cuda_runtime.h>
#include <math.h>

// Problem constants
#define B_   16
#define C_   256
#define HH_  64
#define WW_  64
#define N_   4096      // HH*WW
#define K_   16
#define H_   4
#define U_   4
#define R_   23
#define DV_  64
#define EPS_ 1e-3f

// Scratch (device globals; no allocation allowed)
__device__ float g_wfold[384 * 256];
__device__ float g_bias[384];
__device__ float g_proj[(size_t)B_ * 384 * N_];            // rows 0-63 q, 64-127 k, 128-383 v
__device__ float g_LcPart[(size_t)B_ * 32 * 1024];
__device__ float g_Lc[B_ * K_ * DV_];
__device__ float g_Lp[(size_t)B_ * K_ * DV_ * N_];

// ---- packed fp32x2 helpers (FFMA2 — only reachable via PTX) ----------------
__device__ __forceinline__ unsigned long long pk2(float lo, float hi) {
    unsigned long long r;
    asm("mov.b64 %0, {%1, %2};" : "=l"(r) : "f"(lo), "f"(hi));
    return r;
}
__device__ __forceinline__ void ffma2(unsigned long long& d, unsigned long long a,
                                      unsigned long long b) {
    asm("fma.rn.f32x2 %0, %1, %2, %0;" : "+l"(d) : "l"(a), "l"(b));
}
__device__ __forceinline__ float2 upk2(unsigned long long v) {
    float2 r;
    asm("mov.b64 {%0, %1}, %2;" : "=f"(r.x), "=f"(r.y) : "l"(v));
    return r;
}

// ---------------------------------------------------------------------------
// K1: fold BN into projection weights. o<64: q, o<128: k (no BN), o<384: v
// ---------------------------------------------------------------------------
__global__ void fold_kernel(const float* __restrict__ w_q, const float* __restrict__ w_k,
                            const float* __restrict__ w_v,
                            const float* __restrict__ gq, const float* __restrict__ bq,
                            const float* __restrict__ mq, const float* __restrict__ vq,
                            const float* __restrict__ gv, const float* __restrict__ bv,
                            const float* __restrict__ mv, const float* __restrict__ vvar) {
    int o = blockIdx.x * blockDim.x + threadIdx.x;
    if (o >= 384) return;
    if (o < 64) {
        float inv = gq[o] * rsqrtf(vq[o] + EPS_);
        g_bias[o] = bq[o] - mq[o] * inv;
        for (int c = 0; c < 256; c++) g_wfold[o * 256 + c] = w_q[o * 256 + c] * inv;
    } else if (o < 128) {
        int i = o - 64;
        g_bias[o] = 0.f;
        for (int c = 0; c < 256; c++) g_wfold[o * 256 + c] = w_k[i * 256 + c];
    } else {
        int i = o - 128;
        float inv = gv[i] * rsqrtf(vvar[i] + EPS_);
        g_bias[o] = bv[i] - mv[i] * inv;
        for (int c = 0; c < 256; c++) g_wfold[o * 256 + c] = w_v[i * 256 + c] * inv;
    }
}

// ---------------------------------------------------------------------------
// K2: projection GEMM (FFMA2-packed).  proj[b,o,n] = wfold[o,:]@x[b,:,n]+bias[o]
// ---------------------------------------------------------------------------
__global__ __launch_bounds__(256) void proj_gemm_kernel(const float* __restrict__ x) {
    __shared__ float As[16][64];
    __shared__ float Bs[16][128];
    const int b  = blockIdx.z;
    const int m0 = blockIdx.y * 64;
    const int n0 = blockIdx.x * 128;
    const int tid = threadIdx.x;
    const int tx = tid & 15, ty = tid >> 4;
    const float* xb = x + (size_t)b * C_ * N_ + n0;

    unsigned long long acc[4][4];
#pragma unroll
    for (int j = 0; j < 4; j++)
#pragma unroll
        for (int i = 0; i < 4; i++) acc[j][i] = 0ull;

    for (int k0 = 0; k0 < 256; k0 += 16) {
#pragma unroll
        for (int l = 0; l < 4; l++) {
            int e = tid + l * 256;
            int m = e & 63, kk = e >> 6;
            As[kk][m] = g_wfold[(m0 + m) * 256 + k0 + kk];
        }
#pragma unroll
        for (int l = 0; l < 8; l++) {
            int e = tid + l * 256;
            int kk = e >> 7, n = e & 127;
            Bs[kk][n] = xb[(size_t)(k0 + kk) * N_ + n];
        }
        __syncthreads();
#pragma unroll
        for (int kk = 0; kk < 16; kk++) {
            float4 a4 = *(const float4*)&As[kk][ty * 4];
            float4 b0 = *(const float4*)&Bs[kk][tx * 8];
            float4 b1 = *(const float4*)&Bs[kk][tx * 8 + 4];
            unsigned long long bp[4] = {pk2(b0.x, b0.y), pk2(b0.z, b0.w),
                                        pk2(b1.x, b1.y), pk2(b1.z, b1.w)};
            float av[4] = {a4.x, a4.y, a4.z, a4.w};
#pragma unroll
            for (int j = 0; j < 4; j++) {
                unsigned long long ap = pk2(av[j], av[j]);
#pragma unroll
                for (int i = 0; i < 4; i++) ffma2(acc[j][i], ap, bp[i]);
            }
        }
        __syncthreads();
    }
#pragma unroll
    for (int j = 0; j < 4; j++) {
        int m = m0 + ty * 4 + j;
        float bi = g_bias[m];
        float* dst = g_proj + ((size_t)b * 384 + m) * N_ + n0 + tx * 8;
#pragma unroll
        for (int i = 0; i < 4; i++) {
            float2 v = upk2(acc[j][i]);
            dst[i * 2]     = v.x + bi;
            dst[i * 2 + 1] = v.y + bi;
        }
    }
}

// ---------------------------------------------------------------------------
// K3: softmax over positions for k rows (proj rows 64..127), in place.
// ---------------------------------------------------------------------------
__global__ __launch_bounds__(256) void softmax_kernel() {
    __shared__ float red[8];
    const int row = blockIdx.x;
    const int b = row >> 6, r = row & 63;
    float* p = g_proj + ((size_t)b * 384 + 64 + r) * N_;
    const int tid = threadIdx.x, lane = tid & 31, wid = tid >> 5;

    float v[16];
    float mx = -3.4e38f;
#pragma unroll
    for (int l = 0; l < 16; l++) {
        v[l] = p[tid + l * 256];
        mx = fmaxf(mx, v[l]);
    }
#pragma unroll
    for (int o = 16; o; o >>= 1) mx = fmaxf(mx, __shfl_xor_sync(0xffffffffu, mx, o));
    if (!lane) red[wid] = mx;
    __syncthreads();
    mx = red[0];
#pragma unroll
    for (int w = 1; w < 8; w++) mx = fmaxf(mx, red[w]);

    float s = 0.f;
#pragma unroll
    for (int l = 0; l < 16; l++) {
        v[l] = expf(v[l] - mx);
        s += v[l];
    }
#pragma unroll
    for (int o = 16; o; o >>= 1) s += __shfl_xor_sync(0xffffffffu, s, o);
    __syncthreads();
    if (!lane) red[wid] = s;
    __syncthreads();
    s = 0.f;
#pragma unroll
    for (int w = 0; w < 8; w++) s += red[w];
    float inv = 1.0f / s;
#pragma unroll
    for (int l = 0; l < 16; l++) p[tid + l * 256] = v[l] * inv;
}

// ---------------------------------------------------------------------------
// K4a: Lc partials (deterministic, no atomics)
// ---------------------------------------------------------------------------
__global__ __launch_bounds__(256) void lc_partial_kernel() {
    __shared__ float ks[16][64];
    __shared__ float vsm[64][65];
    const int s = blockIdx.x, u = blockIdx.y, b = blockIdx.z;
    const int tid = threadIdx.x;
    const int kk = tid >> 4, vg = tid & 15;
    float acc[4] = {0.f, 0.f, 0.f, 0.f};
    const float* kbase = g_proj + ((size_t)b * 384 + 64 + u * 16) * N_;
    const float* vbase = g_proj + ((size_t)b * 384 + 128 + u * 64) * N_;
    const int m0b = s * 512;

    for (int mc = 0; mc < 512; mc += 64) {
        const int m0 = m0b + mc;
#pragma unroll
        for (int l = 0; l < 4; l++) {
            int e = tid + l * 256;
            ks[e >> 6][e & 63] = kbase[(size_t)(e >> 6) * N_ + m0 + (e & 63)];
        }
#pragma unroll
        for (int l = 0; l < 16; l++) {
            int e = tid + l * 256;
            vsm[e >> 6][e & 63] = vbase[(size_t)(e >> 6) * N_ + m0 + (e & 63)];
        }
        __syncthreads();
#pragma unroll 8
        for (int m = 0; m < 64; m++) {
            float kv = ks[kk][m];
#pragma unroll
            for (int j = 0; j < 4; j++) acc[j] = fmaf(kv, vsm[vg * 4 + j][m], acc[j]);
        }
        __syncthreads();
    }
    float* dst = g_LcPart + (((size_t)b * 4 + u) * 8 + s) * 1024 + kk * 64 + vg * 4;
#pragma unroll
    for (int j = 0; j < 4; j++) dst[j] = acc[j];
}

__global__ void lc_reduce_kernel() {
    const int b = blockIdx.x;
    const int t = threadIdx.x;  // 1024
    float s = 0.f;
#pragma unroll
    for (int p = 0; p < 32; p++) s += g_LcPart[((size_t)b * 32 + p) * 1024 + t];
    g_Lc[b * 1024 + t] = s;
}

// ---------------------------------------------------------------------------
// K5: position conv — FFMA2-packed.
// Thread: 16 px (8 row-pairs) x 8 k. acc packed over row pairs; weights
// broadcast-packed. 64 FFMA2 per tap instead of 128 FFMA.
// ---------------------------------------------------------------------------
__global__ __launch_bounds__(128) void conv_kernel(const float* __restrict__ w_pos,
                                                   const float* __restrict__ b_pos) {
    __shared__ float vs[54 * 54];   // 11.66 KB
    __shared__ float ws[16 * 529];  // 33.86 KB
    const int quad = blockIdx.x;           // 0..3
    const int dv   = blockIdx.y;           // 0..63
    const int b    = blockIdx.z;           // 0..15
    const int Y0 = (quad >> 1) * 32;
    const int X0 = (quad & 1) * 32;
    const int tid = threadIdx.x;
    const int kh  = tid & 1;               // k half
    const int g   = tid >> 1;              // 0..63
    const int col = g & 31;
    const int rb  = (g >> 5) * 16;         // 0 or 16

    unsigned long long acc[8][8];          // [row-pair][k]
#pragma unroll
    for (int i = 0; i < 8; i++)
#pragma unroll
        for (int j = 0; j < 8; j++) acc[i][j] = 0ull;

    for (int u = 0; u < 4; u++) {
        __syncthreads();
        const float* vimg = g_proj + ((size_t)b * 384 + 128 + u * 64 + dv) * N_;
        for (int e = tid; e < 54 * 54; e += 128) {
            int r = e / 54, c = e - r * 54;
            int y = Y0 + r - 11, x = X0 + c - 11;
            float val = 0.f;
            if (y >= 0 && y < 64 && x >= 0 && x < 64) val = vimg[y * 64 + x];
            vs[e] = val;
        }
        for (int e = tid; e < 16 * 529; e += 128) {
            int kk = e / 529, tap = e - kk * 529;
            ws[e] = w_pos[kk * (4 * 529) + u * 529 + tap];
        }
        __syncthreads();

        const float* wbase = ws + (kh * 8) * 529;
#pragma unroll 1
        for (int dy = 0; dy < 23; dy++) {
            const float* vr = vs + (rb + dy) * 54 + col;
            const float* wr = wbase + dy * 23;
#pragma unroll 1
            for (int dx = 0; dx < 23; dx++) {
                unsigned long long wp[8];
#pragma unroll
                for (int j = 0; j < 8; j++) {
                    float w = wr[j * 529 + dx];
                    wp[j] = pk2(w, w);
                }
#pragma unroll
                for (int i = 0; i < 8; i++) {
                    float v0 = vr[(2 * i) * 54 + dx];
                    float v1 = vr[(2 * i + 1) * 54 + dx];
                    unsigned long long vp = pk2(v0, v1);
#pragma unroll
                    for (int j = 0; j < 8; j++) ffma2(acc[i][j], vp, wp[j]);
                }
            }
        }
    }
    // epilogue: Lp[b][k][dv][n] = acc + b_pos[k]
#pragma unroll
    for (int j = 0; j < 8; j++) {
        const int kk = kh * 8 + j;
        const float bp = b_pos[kk];
        float* dst = g_Lp + (((size_t)b * 16 + kk) * 64 + dv) * N_;
#pragma unroll
        for (int i = 0; i < 8; i++) {
            float2 v = upk2(acc[i][j]);
            int n0v = (Y0 + rb + 2 * i) * 64 + X0 + col;
            dst[n0v]      = v.x + bp;
            dst[n0v + 64] = v.y + bp;
        }
    }
}

// ---------------------------------------------------------------------------
// K6: final combine.
// out[b, h*64+dv, n] = sum_k q[b,h,k,n] * (Lc[b,k,dv] + Lp[b,k,dv,n])
// ---------------------------------------------------------------------------
__global__ __launch_bounds__(128) void final_kernel(float* __restrict__ out) {
    __shared__ float qs[64][128];   // 32 KB
    __shared__ float lps[16][128];  // 8 KB
    __shared__ float lcs[16][64];   // 4 KB
    const int n0 = blockIdx.x * 128;
    const int b  = blockIdx.y;
    const int tid = threadIdx.x;

    const float* qbase = g_proj + (size_t)b * 384 * N_ + n0;
    for (int l = 0; l < 64; l++) {
        int e = tid + l * 128;
        qs[e >> 7][e & 127] = qbase[(size_t)(e >> 7) * N_ + (e & 127)];
    }
#pragma unroll
    for (int l = 0; l < 8; l++) {
        int e = tid + l * 128;
        lcs[e >> 6][e & 63] = g_Lc[b * 1024 + e];
    }

    for (int dv = 0; dv < 64; dv++) {
        __syncthreads();
#pragma unroll
        for (int l = 0; l < 16; l++) {
            int e = tid + l * 128;
            int k = e >> 7, n = e & 127;
            lps[k][n] = g_Lp[(((size_t)b * 16 + k) * 64 + dv) * N_ + n0 + n];
        }
        __syncthreads();
        const int px = tid;
#pragma unroll
        for (int h = 0; h < 4; h++) {
            float y = 0.f;
#pragma unroll
            for (int k = 0; k < 16; k++)
                y = fmaf(qs[h * 16 + k][px], lcs[k][dv] + lps[k][px], y);
            out[((size_t)b * 256 + h * 64 + dv) * N_ + n0 + px] = y;
        }
    }
}

// ---------------------------------------------------------------------------
extern "C" void kernel_launch(void* const* d_in, const int* in_sizes, int n_in,
                              void* d_out, int out_size) {
    const float* x     = (const float*)d_in[0];
    const float* w_q   = (const float*)d_in[1];
    const float* w_k   = (const float*)d_in[2];
    const float* w_v   = (const float*)d_in[3];
    const float* gq    = (const float*)d_in[4];
    const float* bq    = (const float*)d_in[5];
    const float* mq    = (const float*)d_in[6];
    const float* vq    = (const float*)d_in[7];
    const float* gv    = (const float*)d_in[8];
    const float* bv    = (const float*)d_in[9];
    const float* mv    = (const float*)d_in[10];
    const float* vvar  = (const float*)d_in[11];
    const float* w_pos = (const float*)d_in[12];
    const float* b_pos = (const float*)d_in[13];
    float* out = (float*)d_out;

    fold_kernel<<<2, 256>>>(w_q, w_k, w_v, gq, bq, mq, vq, gv, bv, mv, vvar);
    proj_gemm_kernel<<<dim3(32, 6, 16), 256>>>(x);
    softmax_kernel<<<1024, 256>>>();
    lc_partial_kernel<<<dim3(8, 4, 16), 256>>>();
    lc_reduce_kernel<<<16, 1024>>>();
    conv_kernel<<<dim3(4, 64, 16), 128>>>(w_pos, b_pos);
    final_kernel<<<dim3(32, 16), 128>>>(out);
}

// round 4
// speedup vs baseline: 1.4292x; 1.2955x over previous
#include <cuda_runtime.h>
#include <math.h>

// Problem constants
#define B_   16
#define C_   256
#define HH_  64
#define WW_  64
#define N_   4096      // HH*WW
#define K_   16
#define H_   4
#define U_   4
#define R_   23
#define DV_  64
#define EPS_ 1e-3f

// Scratch (device globals; no allocation allowed)
__device__ float  g_wfold[384 * 256];
__device__ float  g_bias[384];
__device__ float  g_proj[(size_t)B_ * 384 * N_];          // rows 0-63 q, 64-127 k, 128-383 v
__device__ float  g_LcPart[(size_t)B_ * 32 * 1024];
__device__ float  g_Lc[B_ * K_ * DV_];
__device__ float  g_Lp[(size_t)B_ * K_ * DV_ * N_];       // 268 MB
__device__ float2 g_tw[64];                               // fwd twiddles W_128^j, j<64
__device__ float2 g_What[65 * 1472];                      // [f][k*92 + u*23 + dy]
__device__ float2 g_Rhat[(size_t)262144 * 65];            // [(b*64+dv)*4+u][y][f]  136 MB
__device__ float2 g_Ghat[(size_t)65536 * 16 * 65];        // [(b*64+dv)*64+y][k][f] 545 MB

// ---- packed fp32x2 helpers (kept for proj GEMM) ----------------------------
__device__ __forceinline__ unsigned long long pk2(float lo, float hi) {
    unsigned long long r;
    asm("mov.b64 %0, {%1, %2};" : "=l"(r) : "f"(lo), "f"(hi));
    return r;
}
__device__ __forceinline__ void ffma2(unsigned long long& d, unsigned long long a,
                                      unsigned long long b) {
    asm("fma.rn.f32x2 %0, %1, %2, %0;" : "+l"(d) : "l"(a), "l"(b));
}
__device__ __forceinline__ float2 upk2(unsigned long long v) {
    float2 r;
    asm("mov.b64 {%0, %1}, %2;" : "=f"(r.x), "=f"(r.y) : "l"(v));
    return r;
}

// ---------------------------------------------------------------------------
// warp-cooperative in-place 128-pt complex FFT (DIT radix-2, natural in/out)
// ln: 128 float2 in shared memory owned by this warp.
// ---------------------------------------------------------------------------
__device__ __forceinline__ void warp_fft128(float2* ln, int lane) {
    __syncwarp();
    // bit-reversal permutation (7 bits)
    float2 a0 = ln[lane], a1 = ln[lane + 32], a2 = ln[lane + 64], a3 = ln[lane + 96];
    __syncwarp();
    ln[__brev((unsigned)lane) >> 25]        = a0;
    ln[__brev((unsigned)(lane + 32)) >> 25] = a1;
    ln[__brev((unsigned)(lane + 64)) >> 25] = a2;
    ln[__brev((unsigned)(lane + 96)) >> 25] = a3;
    __syncwarp();
#pragma unroll
    for (int s = 0; s < 7; s++) {
        int half = 1 << s;
#pragma unroll
        for (int t = 0; t < 2; t++) {
            int bf  = lane + t * 32;          // 0..63 butterfly id
            int grp = bf >> s;
            int pos = bf & (half - 1);
            int i0  = (grp << (s + 1)) + pos;
            int i1  = i0 + half;
            float2 w = g_tw[pos << (6 - s)];
            float2 a = ln[i0], b = ln[i1];
            float2 bt = make_float2(b.x * w.x - b.y * w.y, b.x * w.y + b.y * w.x);
            ln[i0] = make_float2(a.x + bt.x, a.y + bt.y);
            ln[i1] = make_float2(a.x - bt.x, a.y - bt.y);
        }
        __syncwarp();
    }
}

// twiddle init: W^j = exp(-2*pi*i*j/128), double precision trig
__global__ void twiddle_kernel() {
    int j = threadIdx.x;
    if (j < 64) {
        double ang = -2.0 * 3.14159265358979323846 * (double)j / 128.0;
        g_tw[j] = make_float2((float)cos(ang), (float)sin(ang));
    }
}

// ---------------------------------------------------------------------------
// K1: fold BN into projection weights
// ---------------------------------------------------------------------------
__global__ void fold_kernel(const float* __restrict__ w_q, const float* __restrict__ w_k,
                            const float* __restrict__ w_v,
                            const float* __restrict__ gq, const float* __restrict__ bq,
                            const float* __restrict__ mq, const float* __restrict__ vq,
                            const float* __restrict__ gv, const float* __restrict__ bv,
                            const float* __restrict__ mv, const float* __restrict__ vvar) {
    int o = blockIdx.x * blockDim.x + threadIdx.x;
    if (o >= 384) return;
    if (o < 64) {
        float inv = gq[o] * rsqrtf(vq[o] + EPS_);
        g_bias[o] = bq[o] - mq[o] * inv;
        for (int c = 0; c < 256; c++) g_wfold[o * 256 + c] = w_q[o * 256 + c] * inv;
    } else if (o < 128) {
        int i = o - 64;
        g_bias[o] = 0.f;
        for (int c = 0; c < 256; c++) g_wfold[o * 256 + c] = w_k[i * 256 + c];
    } else {
        int i = o - 128;
        float inv = gv[i] * rsqrtf(vvar[i] + EPS_);
        g_bias[o] = bv[i] - mv[i] * inv;
        for (int c = 0; c < 256; c++) g_wfold[o * 256 + c] = w_v[i * 256 + c] * inv;
    }
}

// ---------------------------------------------------------------------------
// K2: projection GEMM
// ---------------------------------------------------------------------------
__global__ __launch_bounds__(256) void proj_gemm_kernel(const float* __restrict__ x) {
    __shared__ float As[16][64];
    __shared__ float Bs[16][128];
    const int b  = blockIdx.z;
    const int m0 = blockIdx.y * 64;
    const int n0 = blockIdx.x * 128;
    const int tid = threadIdx.x;
    const int tx = tid & 15, ty = tid >> 4;
    const float* xb = x + (size_t)b * C_ * N_ + n0;

    unsigned long long acc[4][4];
#pragma unroll
    for (int j = 0; j < 4; j++)
#pragma unroll
        for (int i = 0; i < 4; i++) acc[j][i] = 0ull;

    for (int k0 = 0; k0 < 256; k0 += 16) {
#pragma unroll
        for (int l = 0; l < 4; l++) {
            int e = tid + l * 256;
            int m = e & 63, kk = e >> 6;
            As[kk][m] = g_wfold[(m0 + m) * 256 + k0 + kk];
        }
#pragma unroll
        for (int l = 0; l < 8; l++) {
            int e = tid + l * 256;
            int kk = e >> 7, n = e & 127;
            Bs[kk][n] = xb[(size_t)(k0 + kk) * N_ + n];
        }
        __syncthreads();
#pragma unroll
        for (int kk = 0; kk < 16; kk++) {
            float4 a4 = *(const float4*)&As[kk][ty * 4];
            float4 b0 = *(const float4*)&Bs[kk][tx * 8];
            float4 b1 = *(const float4*)&Bs[kk][tx * 8 + 4];
            unsigned long long bp[4] = {pk2(b0.x, b0.y), pk2(b0.z, b0.w),
                                        pk2(b1.x, b1.y), pk2(b1.z, b1.w)};
            float av[4] = {a4.x, a4.y, a4.z, a4.w};
#pragma unroll
            for (int j = 0; j < 4; j++) {
                unsigned long long ap = pk2(av[j], av[j]);
#pragma unroll
                for (int i = 0; i < 4; i++) ffma2(acc[j][i], ap, bp[i]);
            }
        }
        __syncthreads();
    }
#pragma unroll
    for (int j = 0; j < 4; j++) {
        int m = m0 + ty * 4 + j;
        float bi = g_bias[m];
        float* dst = g_proj + ((size_t)b * 384 + m) * N_ + n0 + tx * 8;
#pragma unroll
        for (int i = 0; i < 4; i++) {
            float2 v = upk2(acc[j][i]);
            dst[i * 2]     = v.x + bi;
            dst[i * 2 + 1] = v.y + bi;
        }
    }
}

// ---------------------------------------------------------------------------
// K3: softmax over positions for k rows
// ---------------------------------------------------------------------------
__global__ __launch_bounds__(256) void softmax_kernel() {
    __shared__ float red[8];
    const int row = blockIdx.x;
    const int b = row >> 6, r = row & 63;
    float* p = g_proj + ((size_t)b * 384 + 64 + r) * N_;
    const int tid = threadIdx.x, lane = tid & 31, wid = tid >> 5;

    float v[16];
    float mx = -3.4e38f;
#pragma unroll
    for (int l = 0; l < 16; l++) {
        v[l] = p[tid + l * 256];
        mx = fmaxf(mx, v[l]);
    }
#pragma unroll
    for (int o = 16; o; o >>= 1) mx = fmaxf(mx, __shfl_xor_sync(0xffffffffu, mx, o));
    if (!lane) red[wid] = mx;
    __syncthreads();
    mx = red[0];
#pragma unroll
    for (int w = 1; w < 8; w++) mx = fmaxf(mx, red[w]);

    float s = 0.f;
#pragma unroll
    for (int l = 0; l < 16; l++) {
        v[l] = expf(v[l] - mx);
        s += v[l];
    }
#pragma unroll
    for (int o = 16; o; o >>= 1) s += __shfl_xor_sync(0xffffffffu, s, o);
    __syncthreads();
    if (!lane) red[wid] = s;
    __syncthreads();
    s = 0.f;
#pragma unroll
    for (int w = 0; w < 8; w++) s += red[w];
    float inv = 1.0f / s;
#pragma unroll
    for (int l = 0; l < 16; l++) p[tid + l * 256] = v[l] * inv;
}

// ---------------------------------------------------------------------------
// K4: Lc partials + reduce
// ---------------------------------------------------------------------------
__global__ __launch_bounds__(256) void lc_partial_kernel() {
    __shared__ float ks[16][64];
    __shared__ float vsm[64][65];
    const int s = blockIdx.x, u = blockIdx.y, b = blockIdx.z;
    const int tid = threadIdx.x;
    const int kk = tid >> 4, vg = tid & 15;
    float acc[4] = {0.f, 0.f, 0.f, 0.f};
    const float* kbase = g_proj + ((size_t)b * 384 + 64 + u * 16) * N_;
    const float* vbase = g_proj + ((size_t)b * 384 + 128 + u * 64) * N_;
    const int m0b = s * 512;

    for (int mc = 0; mc < 512; mc += 64) {
        const int m0 = m0b + mc;
#pragma unroll
        for (int l = 0; l < 4; l++) {
            int e = tid + l * 256;
            ks[e >> 6][e & 63] = kbase[(size_t)(e >> 6) * N_ + m0 + (e & 63)];
        }
#pragma unroll
        for (int l = 0; l < 16; l++) {
            int e = tid + l * 256;
            vsm[e >> 6][e & 63] = vbase[(size_t)(e >> 6) * N_ + m0 + (e & 63)];
        }
        __syncthreads();
#pragma unroll 8
        for (int m = 0; m < 64; m++) {
            float kv = ks[kk][m];
#pragma unroll
            for (int j = 0; j < 4; j++) acc[j] = fmaf(kv, vsm[vg * 4 + j][m], acc[j]);
        }
        __syncthreads();
    }
    float* dst = g_LcPart + (((size_t)b * 4 + u) * 8 + s) * 1024 + kk * 64 + vg * 4;
#pragma unroll
    for (int j = 0; j < 4; j++) dst[j] = acc[j];
}

__global__ void lc_reduce_kernel() {
    const int b = blockIdx.x;
    const int t = threadIdx.x;  // 1024
    float s = 0.f;
#pragma unroll
    for (int p = 0; p < 32; p++) s += g_LcPart[((size_t)b * 32 + p) * 1024 + t];
    g_Lc[b * 1024 + t] = s;
}

// ---------------------------------------------------------------------------
// F0: FFT of position kernel rows (flipped, circularly wrapped)
// row id = k*92 + u*23 + dy ; taps over dx.
// w~c[(11-dx) mod 128] = w_pos[k][u][0][dy][dx]
// Store W^hat[f][rowid] for f=0..64.
// ---------------------------------------------------------------------------
__global__ __launch_bounds__(256) void what_kernel(const float* __restrict__ w_pos) {
    __shared__ float2 lines[8][128];
    const int wid = threadIdx.x >> 5, lane = threadIdx.x & 31;
    const int row = blockIdx.x * 8 + wid;
    if (row >= 1472) return;
    const int k = row / 92;
    const int rem = row - k * 92;
    const int u = rem / 23;
    const int dy = rem - u * 23;
    float2* ln = lines[wid];
#pragma unroll
    for (int t = 0; t < 4; t++) ln[lane + t * 32] = make_float2(0.f, 0.f);
    __syncwarp();
    if (lane < 23) {
        float w = w_pos[(size_t)(k * 4 + u) * 529 + dy * 23 + lane];
        ln[(11 - lane) & 127] = make_float2(w, 0.f);
    }
    warp_fft128(ln, lane);
    float2* dstf = g_What;
    dstf[(size_t)lane * 1472 + row]        = ln[lane];
    dstf[(size_t)(lane + 32) * 1472 + row] = ln[lane + 32];
    if (lane == 0) dstf[(size_t)64 * 1472 + row] = ln[64];
}

// ---------------------------------------------------------------------------
// F1: forward FFT of v rows (zero-padded 64->128). Store bins 0..64.
// r = (((b*64+dv)*4+u)*64+y)
// ---------------------------------------------------------------------------
__global__ __launch_bounds__(256) void rhat_kernel() {
    __shared__ float2 lines[8][128];
    const int wid = threadIdx.x >> 5, lane = threadIdx.x & 31;
    const int r = blockIdx.x * 8 + wid;
    const int y  = r & 63;
    const int u  = (r >> 6) & 3;
    const int dv = (r >> 8) & 63;
    const int b  = r >> 14;
    const float* src = g_proj + ((size_t)(b * 384 + 128 + u * 64 + dv)) * N_ + y * 64;
    float2* ln = lines[wid];
    ln[lane]      = make_float2(src[lane], 0.f);
    ln[lane + 32] = make_float2(src[lane + 32], 0.f);
    ln[lane + 64] = make_float2(0.f, 0.f);
    ln[lane + 96] = make_float2(0.f, 0.f);
    warp_fft128(ln, lane);
    float2* dst = g_Rhat + (size_t)r * 65;
    dst[lane]      = ln[lane];
    dst[lane + 32] = ln[lane + 32];
    if (lane == 0) dst[64] = ln[64];
}

// ---------------------------------------------------------------------------
// F2: frequency-domain mix (the heavy kernel, 25G FMA total)
// Ghat[b,dv,y,k,f] = sum_{u,dy} What[f][k,u,dy] * Rhat[b,u,dv,y+dy-11,f]
// block = (dv, b), 512 threads: tid = fi*256 + kg*64 + y  (fi in 0..1, kg 0..3)
// smem: Rs padded [4][86][65] (rows 0..10 / 75..85 zero) + Wfs[2][16][92]
// ---------------------------------------------------------------------------
__global__ __launch_bounds__(512) void f2_mix_kernel() {
    extern __shared__ float2 sm[];
    float2* Rs  = sm;               // 4*86*65 = 22360
    float2* Wfs = sm + 22360;       // 2*16*92 = 2944
    const int dv = blockIdx.x, b = blockIdx.y;
    const int tid = threadIdx.x;
    const int fi = tid >> 8;
    const int kg = (tid >> 6) & 3;
    const int y  = tid & 63;

    // zero-fill Rs
    for (int i = tid; i < 22360; i += 512) Rs[i] = make_float2(0.f, 0.f);
    __syncthreads();
    // load the 64 real rows into rows 11..74
    const size_t rbase = (size_t)((b * 64 + dv) * 4) * 64 * 65;
    for (int i = tid; i < 16640; i += 512) {
        int u = i / 4160;
        int rem = i - u * 4160;
        int yy = rem / 65;
        int f  = rem - yy * 65;
        Rs[(u * 86 + yy + 11) * 65 + f] = g_Rhat[rbase + i];
    }

    for (int f0 = 0; f0 < 65; f0 += 2) {
        __syncthreads();
        for (int i = tid; i < 2944; i += 512) {
            int ff  = i >> 11;            // /2048? no: 1472 per f
            ff = i / 1472;
            int idx = i - ff * 1472;
            int f = f0 + ff; if (f > 64) f = 64;
            Wfs[i] = g_What[(size_t)f * 1472 + idx];
        }
        __syncthreads();
        const int f = f0 + fi;
        if (f > 64) continue;
        float2 a0 = make_float2(0.f, 0.f), a1 = a0, a2 = a0, a3 = a0;
        const float2* wk = Wfs + fi * 1472 + (kg * 4) * 92;
#pragma unroll 1
        for (int u = 0; u < 4; u++) {
            const float2* rp = Rs + (u * 86 + y) * 65 + f;
            const float2* wp = wk + u * 23;
#pragma unroll
            for (int dy = 0; dy < 23; dy++) {
                float2 r  = rp[dy * 65];
                float2 w0 = wp[dy], w1 = wp[92 + dy], w2 = wp[184 + dy], w3 = wp[276 + dy];
                a0.x = fmaf(r.x, w0.x, a0.x); a0.x = fmaf(-r.y, w0.y, a0.x);
                a0.y = fmaf(r.x, w0.y, a0.y); a0.y = fmaf(r.y, w0.x, a0.y);
                a1.x = fmaf(r.x, w1.x, a1.x); a1.x = fmaf(-r.y, w1.y, a1.x);
                a1.y = fmaf(r.x, w1.y, a1.y); a1.y = fmaf(r.y, w1.x, a1.y);
                a2.x = fmaf(r.x, w2.x, a2.x); a2.x = fmaf(-r.y, w2.y, a2.x);
                a2.y = fmaf(r.x, w2.y, a2.y); a2.y = fmaf(r.y, w2.x, a2.y);
                a3.x = fmaf(r.x, w3.x, a3.x); a3.x = fmaf(-r.y, w3.y, a3.x);
                a3.y = fmaf(r.x, w3.y, a3.y); a3.y = fmaf(r.y, w3.x, a3.y);
            }
        }
        size_t gb = ((((size_t)(b * 64 + dv) * 64 + y) * 16) + kg * 4) * 65 + f;
        g_Ghat[gb]           = a0;
        g_Ghat[gb + 65]      = a1;
        g_Ghat[gb + 130]     = a2;
        g_Ghat[gb + 195]     = a3;
    }
}

// ---------------------------------------------------------------------------
// F3: inverse FFT, k-pairs packed as complex. Writes Lp (+bias).
// block = (b,dv,y) = 65536 blocks, 256 thr = 8 warps = 8 k-pairs.
// ---------------------------------------------------------------------------
__global__ __launch_bounds__(256) void f3_inv_kernel(const float* __restrict__ b_pos) {
    __shared__ float2 Gs[16 * 65];
    __shared__ float2 lines[8][128];
    const int bid = blockIdx.x;
    const int y  = bid & 63;
    const int dv = (bid >> 6) & 63;
    const int b  = bid >> 12;
    const int tid = threadIdx.x;
    const size_t gbase = (size_t)bid * (16 * 65);
    for (int i = tid; i < 1040; i += 256) Gs[i] = g_Ghat[gbase + i];
    __syncthreads();

    const int wid = tid >> 5, lane = tid & 31;
    const int k0 = wid * 2, k1 = k0 + 1;
    float2* Z = lines[wid];
    const float2* G0 = Gs + k0 * 65;
    const float2* G1 = Gs + k1 * 65;
#pragma unroll
    for (int t = 0; t < 4; t++) {
        int f = lane + t * 32;
        float2 z;
        if (f <= 64) {
            float2 a = G0[f], c = G1[f];
            z = make_float2(a.x - c.y, a.y + c.x);          // G0 + i*G1
        } else {
            int g = 128 - f;
            float2 a = G0[g], c = G1[g];
            z = make_float2(a.x + c.y, -a.y + c.x);         // conj(G0)+i*conj(G1)
        }
        Z[f] = make_float2(z.x, -z.y);                      // conj for inverse trick
    }
    warp_fft128(Z, lane);
    // z[x] = conj(fft(conj(Z)))[x]/128 ; lp0 = Re, lp1 = Im
    const float sc = 1.0f / 128.0f;
    const float bp0 = b_pos[k0], bp1 = b_pos[k1];
    float* d0 = g_Lp + (((size_t)(b * 16 + k0) * 64 + dv)) * N_ + y * 64;
    float* d1 = g_Lp + (((size_t)(b * 16 + k1) * 64 + dv)) * N_ + y * 64;
#pragma unroll
    for (int t = 0; t < 2; t++) {
        int x = lane + t * 32;
        float2 o = Z[x];
        d0[x] = o.x * sc + bp0;
        d1[x] = -o.y * sc + bp1;
    }
}

// ---------------------------------------------------------------------------
// K6: final combine
// ---------------------------------------------------------------------------
__global__ __launch_bounds__(128) void final_kernel(float* __restrict__ out) {
    __shared__ float qs[64][128];
    __shared__ float lps[16][128];
    __shared__ float lcs[16][64];
    const int n0 = blockIdx.x * 128;
    const int b  = blockIdx.y;
    const int tid = threadIdx.x;

    const float* qbase = g_proj + (size_t)b * 384 * N_ + n0;
    for (int l = 0; l < 64; l++) {
        int e = tid + l * 128;
        qs[e >> 7][e & 127] = qbase[(size_t)(e >> 7) * N_ + (e & 127)];
    }
#pragma unroll
    for (int l = 0; l < 8; l++) {
        int e = tid + l * 128;
        lcs[e >> 6][e & 63] = g_Lc[b * 1024 + e];
    }

    for (int dv = 0; dv < 64; dv++) {
        __syncthreads();
#pragma unroll
        for (int l = 0; l < 16; l++) {
            int e = tid + l * 128;
            int k = e >> 7, n = e & 127;
            lps[k][n] = g_Lp[(((size_t)b * 16 + k) * 64 + dv) * N_ + n0 + n];
        }
        __syncthreads();
        const int px = tid;
#pragma unroll
        for (int h = 0; h < 4; h++) {
            float y = 0.f;
#pragma unroll
            for (int k = 0; k < 16; k++)
                y = fmaf(qs[h * 16 + k][px], lcs[k][dv] + lps[k][px], y);
            out[((size_t)b * 256 + h * 64 + dv) * N_ + n0 + px] = y;
        }
    }
}

// ---------------------------------------------------------------------------
extern "C" void kernel_launch(void* const* d_in, const int* in_sizes, int n_in,
                              void* d_out, int out_size) {
    const float* x     = (const float*)d_in[0];
    const float* w_q   = (const float*)d_in[1];
    const float* w_k   = (const float*)d_in[2];
    const float* w_v   = (const float*)d_in[3];
    const float* gq    = (const float*)d_in[4];
    const float* bq    = (const float*)d_in[5];
    const float* mq    = (const float*)d_in[6];
    const float* vq    = (const float*)d_in[7];
    const float* gv    = (const float*)d_in[8];
    const float* bv    = (const float*)d_in[9];
    const float* mv    = (const float*)d_in[10];
    const float* vvar  = (const float*)d_in[11];
    const float* w_pos = (const float*)d_in[12];
    const float* b_pos = (const float*)d_in[13];
    float* out = (float*)d_out;

    const int F2_SMEM = 25304 * sizeof(float2);   // 202,432 B
    cudaFuncSetAttribute(f2_mix_kernel, cudaFuncAttributeMaxDynamicSharedMemorySize, F2_SMEM);

    twiddle_kernel<<<1, 64>>>();
    fold_kernel<<<2, 256>>>(w_q, w_k, w_v, gq, bq, mq, vq, gv, bv, mv, vvar);
    proj_gemm_kernel<<<dim3(32, 6, 16), 256>>>(x);
    softmax_kernel<<<1024, 256>>>();
    lc_partial_kernel<<<dim3(8, 4, 16), 256>>>();
    lc_reduce_kernel<<<16, 1024>>>();
    what_kernel<<<184, 256>>>(w_pos);
    rhat_kernel<<<32768, 256>>>();
    f2_mix_kernel<<<dim3(64, 16), 512, F2_SMEM>>>();
    f3_inv_kernel<<<65536, 256>>>(b_pos);
    final_kernel<<<dim3(32, 16), 128>>>(out);
}

// round 5
// speedup vs baseline: 1.5005x; 1.0499x over previous
#include <cuda_runtime.h>
#include <math.h>

// Problem constants
#define B_   16
#define C_   256
#define HH_  64
#define WW_  64
#define N_   4096      // HH*WW
#define K_   16
#define H_   4
#define U_   4
#define R_   23
#define DV_  64
#define EPS_ 1e-3f

#define WSTRIDE 66     // f-stride of W-hat table (float2 units)

// Scratch (device globals; no allocation allowed)
__device__ float  g_wfold[384 * 256];
__device__ float  g_bias[384];
__device__ float  g_proj[(size_t)B_ * 384 * N_];          // rows 0-63 q, 64-127 k, 128-383 v
__device__ float  g_LcPart[(size_t)B_ * 32 * 1024];
__device__ float  g_Lc[B_ * K_ * DV_];
__device__ float  g_Lp[(size_t)B_ * K_ * DV_ * N_];       // 268 MB
__device__ float2 g_tw[64];                               // fwd twiddles W_128^j
__device__ float2 g_What2[1472 * WSTRIDE];                // [row = k*92+u*23+dy][f]
__device__ float2 g_Rhat[(size_t)262144 * 65];            // [(b*64+dv)*4+u][y][f]

// ---- packed fp32x2 helpers (proj GEMM) -------------------------------------
__device__ __forceinline__ unsigned long long pk2(float lo, float hi) {
    unsigned long long r;
    asm("mov.b64 %0, {%1, %2};" : "=l"(r) : "f"(lo), "f"(hi));
    return r;
}
__device__ __forceinline__ void ffma2(unsigned long long& d, unsigned long long a,
                                      unsigned long long b) {
    asm("fma.rn.f32x2 %0, %1, %2, %0;" : "+l"(d) : "l"(a), "l"(b));
}
__device__ __forceinline__ float2 upk2(unsigned long long v) {
    float2 r;
    asm("mov.b64 {%0, %1}, %2;" : "=f"(r.x), "=f"(r.y) : "l"(v));
    return r;
}

// ---------------------------------------------------------------------------
// warp-cooperative in-place 128-pt complex FFT (DIT radix-2, natural order)
// ---------------------------------------------------------------------------
__device__ __forceinline__ void warp_fft128(float2* ln, int lane) {
    __syncwarp();
    float2 a0 = ln[lane], a1 = ln[lane + 32], a2 = ln[lane + 64], a3 = ln[lane + 96];
    __syncwarp();
    ln[__brev((unsigned)lane) >> 25]        = a0;
    ln[__brev((unsigned)(lane + 32)) >> 25] = a1;
    ln[__brev((unsigned)(lane + 64)) >> 25] = a2;
    ln[__brev((unsigned)(lane + 96)) >> 25] = a3;
    __syncwarp();
#pragma unroll
    for (int s = 0; s < 7; s++) {
        int half = 1 << s;
#pragma unroll
        for (int t = 0; t < 2; t++) {
            int bf  = lane + t * 32;
            int grp = bf >> s;
            int pos = bf & (half - 1);
            int i0  = (grp << (s + 1)) + pos;
            int i1  = i0 + half;
            float2 w = g_tw[pos << (6 - s)];
            float2 a = ln[i0], b = ln[i1];
            float2 bt = make_float2(b.x * w.x - b.y * w.y, b.x * w.y + b.y * w.x);
            ln[i0] = make_float2(a.x + bt.x, a.y + bt.y);
            ln[i1] = make_float2(a.x - bt.x, a.y - bt.y);
        }
        __syncwarp();
    }
}

__global__ void twiddle_kernel() {
    int j = threadIdx.x;
    if (j < 64) {
        double ang = -2.0 * 3.14159265358979323846 * (double)j / 128.0;
        g_tw[j] = make_float2((float)cos(ang), (float)sin(ang));
    }
}

// ---------------------------------------------------------------------------
// K1: fold BN into projection weights
// ---------------------------------------------------------------------------
__global__ void fold_kernel(const float* __restrict__ w_q, const float* __restrict__ w_k,
                            const float* __restrict__ w_v,
                            const float* __restrict__ gq, const float* __restrict__ bq,
                            const float* __restrict__ mq, const float* __restrict__ vq,
                            const float* __restrict__ gv, const float* __restrict__ bv,
                            const float* __restrict__ mv, const float* __restrict__ vvar) {
    int o = blockIdx.x * blockDim.x + threadIdx.x;
    if (o >= 384) return;
    if (o < 64) {
        float inv = gq[o] * rsqrtf(vq[o] + EPS_);
        g_bias[o] = bq[o] - mq[o] * inv;
        for (int c = 0; c < 256; c++) g_wfold[o * 256 + c] = w_q[o * 256 + c] * inv;
    } else if (o < 128) {
        int i = o - 64;
        g_bias[o] = 0.f;
        for (int c = 0; c < 256; c++) g_wfold[o * 256 + c] = w_k[i * 256 + c];
    } else {
        int i = o - 128;
        float inv = gv[i] * rsqrtf(vvar[i] + EPS_);
        g_bias[o] = bv[i] - mv[i] * inv;
        for (int c = 0; c < 256; c++) g_wfold[o * 256 + c] = w_v[i * 256 + c] * inv;
    }
}

// ---------------------------------------------------------------------------
// K2: projection GEMM
// ---------------------------------------------------------------------------
__global__ __launch_bounds__(256) void proj_gemm_kernel(const float* __restrict__ x) {
    __shared__ float As[16][64];
    __shared__ float Bs[16][128];
    const int b  = blockIdx.z;
    const int m0 = blockIdx.y * 64;
    const int n0 = blockIdx.x * 128;
    const int tid = threadIdx.x;
    const int tx = tid & 15, ty = tid >> 4;
    const float* xb = x + (size_t)b * C_ * N_ + n0;

    unsigned long long acc[4][4];
#pragma unroll
    for (int j = 0; j < 4; j++)
#pragma unroll
        for (int i = 0; i < 4; i++) acc[j][i] = 0ull;

    for (int k0 = 0; k0 < 256; k0 += 16) {
#pragma unroll
        for (int l = 0; l < 4; l++) {
            int e = tid + l * 256;
            int m = e & 63, kk = e >> 6;
            As[kk][m] = g_wfold[(m0 + m) * 256 + k0 + kk];
        }
#pragma unroll
        for (int l = 0; l < 8; l++) {
            int e = tid + l * 256;
            int kk = e >> 7, n = e & 127;
            Bs[kk][n] = xb[(size_t)(k0 + kk) * N_ + n];
        }
        __syncthreads();
#pragma unroll
        for (int kk = 0; kk < 16; kk++) {
            float4 a4 = *(const float4*)&As[kk][ty * 4];
            float4 b0 = *(const float4*)&Bs[kk][tx * 8];
            float4 b1 = *(const float4*)&Bs[kk][tx * 8 + 4];
            unsigned long long bp[4] = {pk2(b0.x, b0.y), pk2(b0.z, b0.w),
                                        pk2(b1.x, b1.y), pk2(b1.z, b1.w)};
            float av[4] = {a4.x, a4.y, a4.z, a4.w};
#pragma unroll
            for (int j = 0; j < 4; j++) {
                unsigned long long ap = pk2(av[j], av[j]);
#pragma unroll
                for (int i = 0; i < 4; i++) ffma2(acc[j][i], ap, bp[i]);
            }
        }
        __syncthreads();
    }
#pragma unroll
    for (int j = 0; j < 4; j++) {
        int m = m0 + ty * 4 + j;
        float bi = g_bias[m];
        float* dst = g_proj + ((size_t)b * 384 + m) * N_ + n0 + tx * 8;
#pragma unroll
        for (int i = 0; i < 4; i++) {
            float2 v = upk2(acc[j][i]);
            dst[i * 2]     = v.x + bi;
            dst[i * 2 + 1] = v.y + bi;
        }
    }
}

// ---------------------------------------------------------------------------
// K3: softmax over positions for k rows
// ---------------------------------------------------------------------------
__global__ __launch_bounds__(256) void softmax_kernel() {
    __shared__ float red[8];
    const int row = blockIdx.x;
    const int b = row >> 6, r = row & 63;
    float* p = g_proj + ((size_t)b * 384 + 64 + r) * N_;
    const int tid = threadIdx.x, lane = tid & 31, wid = tid >> 5;

    float v[16];
    float mx = -3.4e38f;
#pragma unroll
    for (int l = 0; l < 16; l++) {
        v[l] = p[tid + l * 256];
        mx = fmaxf(mx, v[l]);
    }
#pragma unroll
    for (int o = 16; o; o >>= 1) mx = fmaxf(mx, __shfl_xor_sync(0xffffffffu, mx, o));
    if (!lane) red[wid] = mx;
    __syncthreads();
    mx = red[0];
#pragma unroll
    for (int w = 1; w < 8; w++) mx = fmaxf(mx, red[w]);

    float s = 0.f;
#pragma unroll
    for (int l = 0; l < 16; l++) {
        v[l] = expf(v[l] - mx);
        s += v[l];
    }
#pragma unroll
    for (int o = 16; o; o >>= 1) s += __shfl_xor_sync(0xffffffffu, s, o);
    __syncthreads();
    if (!lane) red[wid] = s;
    __syncthreads();
    s = 0.f;
#pragma unroll
    for (int w = 0; w < 8; w++) s += red[w];
    float inv = 1.0f / s;
#pragma unroll
    for (int l = 0; l < 16; l++) p[tid + l * 256] = v[l] * inv;
}

// ---------------------------------------------------------------------------
// K4: Lc partials + reduce
// ---------------------------------------------------------------------------
__global__ __launch_bounds__(256) void lc_partial_kernel() {
    __shared__ float ks[16][64];
    __shared__ float vsm[64][65];
    const int s = blockIdx.x, u = blockIdx.y, b = blockIdx.z;
    const int tid = threadIdx.x;
    const int kk = tid >> 4, vg = tid & 15;
    float acc[4] = {0.f, 0.f, 0.f, 0.f};
    const float* kbase = g_proj + ((size_t)b * 384 + 64 + u * 16) * N_;
    const float* vbase = g_proj + ((size_t)b * 384 + 128 + u * 64) * N_;
    const int m0b = s * 512;

    for (int mc = 0; mc < 512; mc += 64) {
        const int m0 = m0b + mc;
#pragma unroll
        for (int l = 0; l < 4; l++) {
            int e = tid + l * 256;
            ks[e >> 6][e & 63] = kbase[(size_t)(e >> 6) * N_ + m0 + (e & 63)];
        }
#pragma unroll
        for (int l = 0; l < 16; l++) {
            int e = tid + l * 256;
            vsm[e >> 6][e & 63] = vbase[(size_t)(e >> 6) * N_ + m0 + (e & 63)];
        }
        __syncthreads();
#pragma unroll 8
        for (int m = 0; m < 64; m++) {
            float kv = ks[kk][m];
#pragma unroll
            for (int j = 0; j < 4; j++) acc[j] = fmaf(kv, vsm[vg * 4 + j][m], acc[j]);
        }
        __syncthreads();
    }
    float* dst = g_LcPart + (((size_t)b * 4 + u) * 8 + s) * 1024 + kk * 64 + vg * 4;
#pragma unroll
    for (int j = 0; j < 4; j++) dst[j] = acc[j];
}

__global__ void lc_reduce_kernel() {
    const int b = blockIdx.x;
    const int t = threadIdx.x;  // 1024
    float s = 0.f;
#pragma unroll
    for (int p = 0; p < 32; p++) s += g_LcPart[((size_t)b * 32 + p) * 1024 + t];
    g_Lc[b * 1024 + t] = s;
}

// ---------------------------------------------------------------------------
// F0: FFT of position kernel rows (flipped, circularly wrapped)
// Store g_What2[row*WSTRIDE + f], row = k*92 + u*23 + dy, f = 0..64.
// ---------------------------------------------------------------------------
__global__ __launch_bounds__(256) void what_kernel(const float* __restrict__ w_pos) {
    __shared__ float2 lines[8][128];
    const int wid = threadIdx.x >> 5, lane = threadIdx.x & 31;
    const int row = blockIdx.x * 8 + wid;
    if (row >= 1472) return;
    const int k = row / 92;
    const int rem = row - k * 92;
    const int u = rem / 23;
    const int dy = rem - u * 23;
    float2* ln = lines[wid];
#pragma unroll
    for (int t = 0; t < 4; t++) ln[lane + t * 32] = make_float2(0.f, 0.f);
    __syncwarp();
    if (lane < 23) {
        float w = w_pos[(size_t)(k * 4 + u) * 529 + dy * 23 + lane];
        ln[(11 - lane) & 127] = make_float2(w, 0.f);
    }
    warp_fft128(ln, lane);
    g_What2[(size_t)row * WSTRIDE + lane]      = ln[lane];
    g_What2[(size_t)row * WSTRIDE + lane + 32] = ln[lane + 32];
    if (lane == 0) g_What2[(size_t)row * WSTRIDE + 64] = ln[64];
}

// ---------------------------------------------------------------------------
// F1: forward FFT of v rows (zero-padded 64->128). Store bins 0..64.
// ---------------------------------------------------------------------------
__global__ __launch_bounds__(256) void rhat_kernel() {
    __shared__ float2 lines[8][128];
    const int wid = threadIdx.x >> 5, lane = threadIdx.x & 31;
    const int r = blockIdx.x * 8 + wid;
    const int y  = r & 63;
    const int u  = (r >> 6) & 3;
    const int dv = (r >> 8) & 63;
    const int b  = r >> 14;
    const float* src = g_proj + ((size_t)(b * 384 + 128 + u * 64 + dv)) * N_ + y * 64;
    float2* ln = lines[wid];
    ln[lane]      = make_float2(src[lane], 0.f);
    ln[lane + 32] = make_float2(src[lane + 32], 0.f);
    ln[lane + 64] = make_float2(0.f, 0.f);
    ln[lane + 96] = make_float2(0.f, 0.f);
    warp_fft128(ln, lane);
    float2* dst = g_Rhat + (size_t)r * 65;
    dst[lane]      = ln[lane];
    dst[lane + 32] = ln[lane + 32];
    if (lane == 0) dst[64] = ln[64];
}

// ---------------------------------------------------------------------------
// F2F3 fused: frequency mix + inverse FFT, writes Lp directly.
// block = (dv, b), 256 thr = 8 warps = (kq 0..3) x (fc 0..1).
// Loop over 4 y-tiles of 16:
//   - stage Rs = Rhat halo [4u][38 rows][65 f]   (79 KB)
//   - mix: thread owns (kq, f=fc*32+lane), 8y x 4k complex acc per yhalf
//       W loaded coalesced from g_What2 (f-contiguous rows)
//   - f=64 Nyquist bin: one (y,k) cell per thread
//   - inverse: 8 warps x 16 lines (k-pairs hermitian-packed), write Lp
// smem: Gs 16640 + Rs 9880 float2 = 212,160 B (lines alias Rs)
// ---------------------------------------------------------------------------
__global__ __launch_bounds__(256) void f2f3_fused_kernel(const float* __restrict__ b_pos) {
    extern __shared__ float2 sm[];
    float2* Gs = sm;                 // 16*16*65 = 16640
    float2* Rs = sm + 16640;         // 4*38*65  = 9880
    const int dv = blockIdx.x, b = blockIdx.y;
    const int tid  = threadIdx.x;
    const int lane = tid & 31;
    const int wrp  = tid >> 5;       // 0..7
    const int kq   = wrp & 3;
    const int fc   = wrp >> 2;       // 0..1
    const int f    = fc * 32 + lane; // 0..63
    const int bdv  = b * 64 + dv;

    // per-thread f64-phase cell
    const int c_y = tid >> 4, c_k = tid & 15;
    // inverse-phase constants: warp -> k-pair
    const int k0 = wrp * 2, k1 = k0 + 1;
    const float bp0 = b_pos[k0], bp1 = b_pos[k1];
    const float sc = 1.0f / 128.0f;
    float2* Z = Rs + wrp * 128;      // line buffer alias (Rs dead during inverse)

    for (int yt = 0; yt < 4; yt++) {
        const int y0 = yt * 16;
        __syncthreads();             // protect Rs/lines from previous phase
        // stage Rs: rows rr=0..37 <-> global y = y0 + rr - 11
        for (int i = tid; i < 9880; i += 256) {
            int u  = i / 2470;
            int rem = i - u * 2470;
            int rr = rem / 65;
            int ff = rem - rr * 65;
            int y  = y0 + rr - 11;
            float2 val = make_float2(0.f, 0.f);
            if (y >= 0 && y < 64)
                val = g_Rhat[(((size_t)bdv * 4 + u) * 64 + y) * 65 + ff];
            Rs[i] = val;
        }
        __syncthreads();

        // ---- mix: f = 0..63 ----
#pragma unroll
        for (int yh = 0; yh < 2; yh++) {
            float2 acc[8][4];
#pragma unroll
            for (int i = 0; i < 8; i++)
#pragma unroll
                for (int j = 0; j < 4; j++) acc[i][j] = make_float2(0.f, 0.f);

#pragma unroll 1
            for (int u = 0; u < 4; u++) {
                const float2* rptr = Rs + (u * 38 + yh * 8) * 65 + f;
                const float2* w0p = g_What2 + ((size_t)((kq * 4 + 0) * 4 + u) * 23) * WSTRIDE + f;
                const float2* w1p = g_What2 + ((size_t)((kq * 4 + 1) * 4 + u) * 23) * WSTRIDE + f;
                const float2* w2p = g_What2 + ((size_t)((kq * 4 + 2) * 4 + u) * 23) * WSTRIDE + f;
                const float2* w3p = g_What2 + ((size_t)((kq * 4 + 3) * 4 + u) * 23) * WSTRIDE + f;
#pragma unroll 1
                for (int dy = 0; dy < 23; dy++) {
                    float2 w0 = *w0p, w1 = *w1p, w2 = *w2p, w3 = *w3p;
#pragma unroll
                    for (int i = 0; i < 8; i++) {
                        float2 r = rptr[i * 65];
                        acc[i][0].x = fmaf(r.x, w0.x, acc[i][0].x);
                        acc[i][0].x = fmaf(-r.y, w0.y, acc[i][0].x);
                        acc[i][0].y = fmaf(r.x, w0.y, acc[i][0].y);
                        acc[i][0].y = fmaf(r.y, w0.x, acc[i][0].y);
                        acc[i][1].x = fmaf(r.x, w1.x, acc[i][1].x);
                        acc[i][1].x = fmaf(-r.y, w1.y, acc[i][1].x);
                        acc[i][1].y = fmaf(r.x, w1.y, acc[i][1].y);
                        acc[i][1].y = fmaf(r.y, w1.x, acc[i][1].y);
                        acc[i][2].x = fmaf(r.x, w2.x, acc[i][2].x);
                        acc[i][2].x = fmaf(-r.y, w2.y, acc[i][2].x);
                        acc[i][2].y = fmaf(r.x, w2.y, acc[i][2].y);
                        acc[i][2].y = fmaf(r.y, w2.x, acc[i][2].y);
                        acc[i][3].x = fmaf(r.x, w3.x, acc[i][3].x);
                        acc[i][3].x = fmaf(-r.y, w3.y, acc[i][3].x);
                        acc[i][3].y = fmaf(r.x, w3.y, acc[i][3].y);
                        acc[i][3].y = fmaf(r.y, w3.x, acc[i][3].y);
                    }
                    rptr += 65;
                    w0p += WSTRIDE; w1p += WSTRIDE; w2p += WSTRIDE; w3p += WSTRIDE;
                }
            }
            // write to Gs
#pragma unroll
            for (int i = 0; i < 8; i++)
#pragma unroll
                for (int j = 0; j < 4; j++)
                    Gs[((yh * 8 + i) * 16 + kq * 4 + j) * 65 + f] = acc[i][j];
        }

        // ---- f = 64 bin (one (y,k) cell per thread) ----
        {
            float2 a = make_float2(0.f, 0.f);
#pragma unroll 1
            for (int u = 0; u < 4; u++) {
                const float2* rptr = Rs + (u * 38 + c_y) * 65 + 64;
                const float2* wp = g_What2 + ((size_t)(c_k * 4 + u) * 23) * WSTRIDE + 64;
#pragma unroll
                for (int dy = 0; dy < 23; dy++) {
                    float2 r = rptr[dy * 65];
                    float2 w = wp[dy * WSTRIDE];
                    a.x = fmaf(r.x, w.x, a.x); a.x = fmaf(-r.y, w.y, a.x);
                    a.y = fmaf(r.x, w.y, a.y); a.y = fmaf(r.y, w.x, a.y);
                }
            }
            Gs[(c_y * 16 + c_k) * 65 + 64] = a;
        }
        __syncthreads();   // Gs complete; Rs free for line buffers

        // ---- inverse: warp = k-pair, 16 y lines each ----
        for (int yl = 0; yl < 16; yl++) {
            const float2* G0 = Gs + (yl * 16 + k0) * 65;
            const float2* G1 = Gs + (yl * 16 + k1) * 65;
#pragma unroll
            for (int t = 0; t < 4; t++) {
                int ff = lane + t * 32;
                float2 z;
                if (ff <= 64) {
                    float2 a = G0[ff], c = G1[ff];
                    z = make_float2(a.x - c.y, a.y + c.x);
                } else {
                    int g = 128 - ff;
                    float2 a = G0[g], c = G1[g];
                    z = make_float2(a.x + c.y, -a.y + c.x);
                }
                Z[ff] = make_float2(z.x, -z.y);
            }
            warp_fft128(Z, lane);
            const int yg = y0 + yl;
            float* d0 = g_Lp + (((size_t)(b * 16 + k0) * 64 + dv)) * N_ + yg * 64;
            float* d1 = g_Lp + (((size_t)(b * 16 + k1) * 64 + dv)) * N_ + yg * 64;
#pragma unroll
            for (int t = 0; t < 2; t++) {
                int x = lane + t * 32;
                float2 o = Z[x];
                d0[x] = o.x * sc + bp0;
                d1[x] = -o.y * sc + bp1;
            }
        }
    }
}

// ---------------------------------------------------------------------------
// K6: final combine
// ---------------------------------------------------------------------------
__global__ __launch_bounds__(128) void final_kernel(float* __restrict__ out) {
    __shared__ float qs[64][128];
    __shared__ float lps[16][128];
    __shared__ float lcs[16][64];
    const int n0 = blockIdx.x * 128;
    const int b  = blockIdx.y;
    const int tid = threadIdx.x;

    const float* qbase = g_proj + (size_t)b * 384 * N_ + n0;
    for (int l = 0; l < 64; l++) {
        int e = tid + l * 128;
        qs[e >> 7][e & 127] = qbase[(size_t)(e >> 7) * N_ + (e & 127)];
    }
#pragma unroll
    for (int l = 0; l < 8; l++) {
        int e = tid + l * 128;
        lcs[e >> 6][e & 63] = g_Lc[b * 1024 + e];
    }

    for (int dv = 0; dv < 64; dv++) {
        __syncthreads();
#pragma unroll
        for (int l = 0; l < 16; l++) {
            int e = tid + l * 128;
            int k = e >> 7, n = e & 127;
            lps[k][n] = g_Lp[(((size_t)b * 16 + k) * 64 + dv) * N_ + n0 + n];
        }
        __syncthreads();
        const int px = tid;
#pragma unroll
        for (int h = 0; h < 4; h++) {
            float y = 0.f;
#pragma unroll
            for (int k = 0; k < 16; k++)
                y = fmaf(qs[h * 16 + k][px], lcs[k][dv] + lps[k][px], y);
            out[((size_t)b * 256 + h * 64 + dv) * N_ + n0 + px] = y;
        }
    }
}

// ---------------------------------------------------------------------------
extern "C" void kernel_launch(void* const* d_in, const int* in_sizes, int n_in,
                              void* d_out, int out_size) {
    const float* x     = (const float*)d_in[0];
    const float* w_q   = (const float*)d_in[1];
    const float* w_k   = (const float*)d_in[2];
    const float* w_v   = (const float*)d_in[3];
    const float* gq    = (const float*)d_in[4];
    const float* bq    = (const float*)d_in[5];
    const float* mq    = (const float*)d_in[6];
    const float* vq    = (const float*)d_in[7];
    const float* gv    = (const float*)d_in[8];
    const float* bv    = (const float*)d_in[9];
    const float* mv    = (const float*)d_in[10];
    const float* vvar  = (const float*)d_in[11];
    const float* w_pos = (const float*)d_in[12];
    const float* b_pos = (const float*)d_in[13];
    float* out = (float*)d_out;

    const int FUSED_SMEM = (16640 + 9880) * sizeof(float2);   // 212,160 B
    cudaFuncSetAttribute(f2f3_fused_kernel,
                         cudaFuncAttributeMaxDynamicSharedMemorySize, FUSED_SMEM);

    twiddle_kernel<<<1, 64>>>();
    fold_kernel<<<2, 256>>>(w_q, w_k, w_v, gq, bq, mq, vq, gv, bv, mv, vvar);
    proj_gemm_kernel<<<dim3(32, 6, 16), 256>>>(x);
    softmax_kernel<<<1024, 256>>>();
    lc_partial_kernel<<<dim3(8, 4, 16), 256>>>();
    lc_reduce_kernel<<<16, 1024>>>();
    what_kernel<<<184, 256>>>(w_pos);
    rhat_kernel<<<32768, 256>>>();
    f2f3_fused_kernel<<<dim3(64, 16), 256, FUSED_SMEM>>>(b_pos);
    final_kernel<<<dim3(32, 16), 128>>>(out);
}

// round 6
// speedup vs baseline: 1.7329x; 1.1548x over previous
#include <cuda_runtime.h>
#include <math.h>

// Problem constants
#define B_   16
#define C_   256
#define HH_  64
#define WW_  64
#define N_   4096      // HH*WW
#define K_   16
#define H_   4
#define U_   4
#define R_   23
#define DV_  64
#define EPS_ 1e-3f

#define WSTRIDE 66     // f-stride of W-hat table (float2 units)

// Scratch (device globals; no allocation allowed)
__device__ float  g_wfold[384 * 256];
__device__ float  g_bias[384];
__device__ float  g_proj[(size_t)B_ * 384 * N_];          // rows 0-63 q, 64-127 k, 128-383 v
__device__ float  g_LcPart[(size_t)B_ * 32 * 1024];
__device__ float  g_Lc[B_ * K_ * DV_];
__device__ float  g_Lp[(size_t)B_ * K_ * DV_ * N_];       // 268 MB
__device__ float2 g_tw[64];                               // fwd twiddles W_128^j
__device__ float2 g_What2[1472 * WSTRIDE];                // [row = k*92+u*23+dy][f]
__device__ float2 g_Rhat[(size_t)262144 * 65];            // [(b*64+dv)*4+u][y][f]

// ---- packed fp32x2 helpers (proj GEMM) -------------------------------------
__device__ __forceinline__ unsigned long long pk2(float lo, float hi) {
    unsigned long long r;
    asm("mov.b64 %0, {%1, %2};" : "=l"(r) : "f"(lo), "f"(hi));
    return r;
}
__device__ __forceinline__ void ffma2(unsigned long long& d, unsigned long long a,
                                      unsigned long long b) {
    asm("fma.rn.f32x2 %0, %1, %2, %0;" : "+l"(d) : "l"(a), "l"(b));
}
__device__ __forceinline__ float2 upk2(unsigned long long v) {
    float2 r;
    asm("mov.b64 {%0, %1}, %2;" : "=f"(r.x), "=f"(r.y) : "l"(v));
    return r;
}

// ---------------------------------------------------------------------------
// warp-cooperative in-place 128-pt complex FFT (DIT radix-2, natural order)
// ---------------------------------------------------------------------------
__device__ __forceinline__ void warp_fft128(float2* ln, int lane) {
    __syncwarp();
    float2 a0 = ln[lane], a1 = ln[lane + 32], a2 = ln[lane + 64], a3 = ln[lane + 96];
    __syncwarp();
    ln[__brev((unsigned)lane) >> 25]        = a0;
    ln[__brev((unsigned)(lane + 32)) >> 25] = a1;
    ln[__brev((unsigned)(lane + 64)) >> 25] = a2;
    ln[__brev((unsigned)(lane + 96)) >> 25] = a3;
    __syncwarp();
#pragma unroll
    for (int s = 0; s < 7; s++) {
        int half = 1 << s;
#pragma unroll
        for (int t = 0; t < 2; t++) {
            int bf  = lane + t * 32;
            int grp = bf >> s;
            int pos = bf & (half - 1);
            int i0  = (grp << (s + 1)) + pos;
            int i1  = i0 + half;
            float2 w = g_tw[pos << (6 - s)];
            float2 a = ln[i0], b = ln[i1];
            float2 bt = make_float2(b.x * w.x - b.y * w.y, b.x * w.y + b.y * w.x);
            ln[i0] = make_float2(a.x + bt.x, a.y + bt.y);
            ln[i1] = make_float2(a.x - bt.x, a.y - bt.y);
        }
        __syncwarp();
    }
}

__global__ void twiddle_kernel() {
    int j = threadIdx.x;
    if (j < 64) {
        double ang = -2.0 * 3.14159265358979323846 * (double)j / 128.0;
        g_tw[j] = make_float2((float)cos(ang), (float)sin(ang));
    }
}

// ---------------------------------------------------------------------------
// K1: fold BN into projection weights
// ---------------------------------------------------------------------------
__global__ void fold_kernel(const float* __restrict__ w_q, const float* __restrict__ w_k,
                            const float* __restrict__ w_v,
                            const float* __restrict__ gq, const float* __restrict__ bq,
                            const float* __restrict__ mq, const float* __restrict__ vq,
                            const float* __restrict__ gv, const float* __restrict__ bv,
                            const float* __restrict__ mv, const float* __restrict__ vvar) {
    int o = blockIdx.x * blockDim.x + threadIdx.x;
    if (o >= 384) return;
    if (o < 64) {
        float inv = gq[o] * rsqrtf(vq[o] + EPS_);
        g_bias[o] = bq[o] - mq[o] * inv;
        for (int c = 0; c < 256; c++) g_wfold[o * 256 + c] = w_q[o * 256 + c] * inv;
    } else if (o < 128) {
        int i = o - 64;
        g_bias[o] = 0.f;
        for (int c = 0; c < 256; c++) g_wfold[o * 256 + c] = w_k[i * 256 + c];
    } else {
        int i = o - 128;
        float inv = gv[i] * rsqrtf(vvar[i] + EPS_);
        g_bias[o] = bv[i] - mv[i] * inv;
        for (int c = 0; c < 256; c++) g_wfold[o * 256 + c] = w_v[i * 256 + c] * inv;
    }
}

// ---------------------------------------------------------------------------
// K2: projection GEMM
// ---------------------------------------------------------------------------
__global__ __launch_bounds__(256) void proj_gemm_kernel(const float* __restrict__ x) {
    __shared__ float As[16][64];
    __shared__ float Bs[16][128];
    const int b  = blockIdx.z;
    const int m0 = blockIdx.y * 64;
    const int n0 = blockIdx.x * 128;
    const int tid = threadIdx.x;
    const int tx = tid & 15, ty = tid >> 4;
    const float* xb = x + (size_t)b * C_ * N_ + n0;

    unsigned long long acc[4][4];
#pragma unroll
    for (int j = 0; j < 4; j++)
#pragma unroll
        for (int i = 0; i < 4; i++) acc[j][i] = 0ull;

    for (int k0 = 0; k0 < 256; k0 += 16) {
#pragma unroll
        for (int l = 0; l < 4; l++) {
            int e = tid + l * 256;
            int m = e & 63, kk = e >> 6;
            As[kk][m] = g_wfold[(m0 + m) * 256 + k0 + kk];
        }
#pragma unroll
        for (int l = 0; l < 8; l++) {
            int e = tid + l * 256;
            int kk = e >> 7, n = e & 127;
            Bs[kk][n] = xb[(size_t)(k0 + kk) * N_ + n];
        }
        __syncthreads();
#pragma unroll
        for (int kk = 0; kk < 16; kk++) {
            float4 a4 = *(const float4*)&As[kk][ty * 4];
            float4 b0 = *(const float4*)&Bs[kk][tx * 8];
            float4 b1 = *(const float4*)&Bs[kk][tx * 8 + 4];
            unsigned long long bp[4] = {pk2(b0.x, b0.y), pk2(b0.z, b0.w),
                                        pk2(b1.x, b1.y), pk2(b1.z, b1.w)};
            float av[4] = {a4.x, a4.y, a4.z, a4.w};
#pragma unroll
            for (int j = 0; j < 4; j++) {
                unsigned long long ap = pk2(av[j], av[j]);
#pragma unroll
                for (int i = 0; i < 4; i++) ffma2(acc[j][i], ap, bp[i]);
            }
        }
        __syncthreads();
    }
#pragma unroll
    for (int j = 0; j < 4; j++) {
        int m = m0 + ty * 4 + j;
        float bi = g_bias[m];
        float* dst = g_proj + ((size_t)b * 384 + m) * N_ + n0 + tx * 8;
#pragma unroll
        for (int i = 0; i < 4; i++) {
            float2 v = upk2(acc[j][i]);
            dst[i * 2]     = v.x + bi;
            dst[i * 2 + 1] = v.y + bi;
        }
    }
}

// ---------------------------------------------------------------------------
// K3: softmax over positions for k rows
// ---------------------------------------------------------------------------
__global__ __launch_bounds__(256) void softmax_kernel() {
    __shared__ float red[8];
    const int row = blockIdx.x;
    const int b = row >> 6, r = row & 63;
    float* p = g_proj + ((size_t)b * 384 + 64 + r) * N_;
    const int tid = threadIdx.x, lane = tid & 31, wid = tid >> 5;

    float v[16];
    float mx = -3.4e38f;
#pragma unroll
    for (int l = 0; l < 16; l++) {
        v[l] = p[tid + l * 256];
        mx = fmaxf(mx, v[l]);
    }
#pragma unroll
    for (int o = 16; o; o >>= 1) mx = fmaxf(mx, __shfl_xor_sync(0xffffffffu, mx, o));
    if (!lane) red[wid] = mx;
    __syncthreads();
    mx = red[0];
#pragma unroll
    for (int w = 1; w < 8; w++) mx = fmaxf(mx, red[w]);

    float s = 0.f;
#pragma unroll
    for (int l = 0; l < 16; l++) {
        v[l] = expf(v[l] - mx);
        s += v[l];
    }
#pragma unroll
    for (int o = 16; o; o >>= 1) s += __shfl_xor_sync(0xffffffffu, s, o);
    __syncthreads();
    if (!lane) red[wid] = s;
    __syncthreads();
    s = 0.f;
#pragma unroll
    for (int w = 0; w < 8; w++) s += red[w];
    float inv = 1.0f / s;
#pragma unroll
    for (int l = 0; l < 16; l++) p[tid + l * 256] = v[l] * inv;
}

// ---------------------------------------------------------------------------
// K4: Lc partials + reduce
// ---------------------------------------------------------------------------
__global__ __launch_bounds__(256) void lc_partial_kernel() {
    __shared__ float ks[16][64];
    __shared__ float vsm[64][65];
    const int s = blockIdx.x, u = blockIdx.y, b = blockIdx.z;
    const int tid = threadIdx.x;
    const int kk = tid >> 4, vg = tid & 15;
    float acc[4] = {0.f, 0.f, 0.f, 0.f};
    const float* kbase = g_proj + ((size_t)b * 384 + 64 + u * 16) * N_;
    const float* vbase = g_proj + ((size_t)b * 384 + 128 + u * 64) * N_;
    const int m0b = s * 512;

    for (int mc = 0; mc < 512; mc += 64) {
        const int m0 = m0b + mc;
#pragma unroll
        for (int l = 0; l < 4; l++) {
            int e = tid + l * 256;
            ks[e >> 6][e & 63] = kbase[(size_t)(e >> 6) * N_ + m0 + (e & 63)];
        }
#pragma unroll
        for (int l = 0; l < 16; l++) {
            int e = tid + l * 256;
            vsm[e >> 6][e & 63] = vbase[(size_t)(e >> 6) * N_ + m0 + (e & 63)];
        }
        __syncthreads();
#pragma unroll 8
        for (int m = 0; m < 64; m++) {
            float kv = ks[kk][m];
#pragma unroll
            for (int j = 0; j < 4; j++) acc[j] = fmaf(kv, vsm[vg * 4 + j][m], acc[j]);
        }
        __syncthreads();
    }
    float* dst = g_LcPart + (((size_t)b * 4 + u) * 8 + s) * 1024 + kk * 64 + vg * 4;
#pragma unroll
    for (int j = 0; j < 4; j++) dst[j] = acc[j];
}

__global__ void lc_reduce_kernel() {
    const int b = blockIdx.x;
    const int t = threadIdx.x;  // 1024
    float s = 0.f;
#pragma unroll
    for (int p = 0; p < 32; p++) s += g_LcPart[((size_t)b * 32 + p) * 1024 + t];
    g_Lc[b * 1024 + t] = s;
}

// ---------------------------------------------------------------------------
// F0: FFT of position kernel rows (flipped, circularly wrapped)
// ---------------------------------------------------------------------------
__global__ __launch_bounds__(256) void what_kernel(const float* __restrict__ w_pos) {
    __shared__ float2 lines[8][128];
    const int wid = threadIdx.x >> 5, lane = threadIdx.x & 31;
    const int row = blockIdx.x * 8 + wid;
    if (row >= 1472) return;
    const int k = row / 92;
    const int rem = row - k * 92;
    const int u = rem / 23;
    const int dy = rem - u * 23;
    float2* ln = lines[wid];
#pragma unroll
    for (int t = 0; t < 4; t++) ln[lane + t * 32] = make_float2(0.f, 0.f);
    __syncwarp();
    if (lane < 23) {
        float w = w_pos[(size_t)(k * 4 + u) * 529 + dy * 23 + lane];
        ln[(11 - lane) & 127] = make_float2(w, 0.f);
    }
    warp_fft128(ln, lane);
    g_What2[(size_t)row * WSTRIDE + lane]      = ln[lane];
    g_What2[(size_t)row * WSTRIDE + lane + 32] = ln[lane + 32];
    if (lane == 0) g_What2[(size_t)row * WSTRIDE + 64] = ln[64];
}

// ---------------------------------------------------------------------------
// F1: forward FFT of v rows (zero-padded 64->128). Store bins 0..64.
// ---------------------------------------------------------------------------
__global__ __launch_bounds__(256) void rhat_kernel() {
    __shared__ float2 lines[8][128];
    const int wid = threadIdx.x >> 5, lane = threadIdx.x & 31;
    const int r = blockIdx.x * 8 + wid;
    const int y  = r & 63;
    const int u  = (r >> 6) & 3;
    const int dv = (r >> 8) & 63;
    const int b  = r >> 14;
    const float* src = g_proj + ((size_t)(b * 384 + 128 + u * 64 + dv)) * N_ + y * 64;
    float2* ln = lines[wid];
    ln[lane]      = make_float2(src[lane], 0.f);
    ln[lane + 32] = make_float2(src[lane + 32], 0.f);
    ln[lane + 64] = make_float2(0.f, 0.f);
    ln[lane + 96] = make_float2(0.f, 0.f);
    warp_fft128(ln, lane);
    float2* dst = g_Rhat + (size_t)r * 65;
    dst[lane]      = ln[lane];
    dst[lane + 32] = ln[lane + 32];
    if (lane == 0) dst[64] = ln[64];
}

// ---------------------------------------------------------------------------
// F2F3 fused (512 threads): frequency mix + inverse FFT, writes Lp directly.
// block = (dv, b), 16 warps: warp = (kq 0..3, fh 0..3).
// lane = (yh 0..1, fl 0..15); f = fh*16 + fl; thread owns 8y x 4k complex acc.
// Loop over 4 y-tiles of 16:
//   - stage Rs halo [4u][38 rows][65 f]
//   - mix (f 0..63), Nyquist f=64 side phase
//   - inverse: 16 warps x 8 lines (k-pairs hermitian-packed), write Lp
// ---------------------------------------------------------------------------
__global__ __launch_bounds__(512) void f2f3_fused_kernel(const float* __restrict__ b_pos) {
    extern __shared__ float2 sm[];
    float2* Gs = sm;                 // 16*16*65 = 16640
    float2* Rs = sm + 16640;         // 4*38*65  = 9880
    const int dv = blockIdx.x, b = blockIdx.y;
    const int tid  = threadIdx.x;
    const int lane = tid & 31;
    const int wrp  = tid >> 5;       // 0..15
    const int kq   = wrp & 3;
    const int fh   = wrp >> 2;       // 0..3
    const int fl   = lane & 15;
    const int f    = fh * 16 + fl;   // 0..63
    const int yh   = lane >> 4;      // 0..1
    const int bdv  = b * 64 + dv;

    // Nyquist-phase cell (threads 0..255)
    const int c_y = tid >> 4, c_k = tid & 15;
    // inverse-phase mapping: warp -> (k-pair, y-half)
    const int ikp   = wrp & 7;
    const int ihalf = wrp >> 3;
    const int k0 = ikp * 2, k1 = k0 + 1;
    const float bp0 = b_pos[k0], bp1 = b_pos[k1];
    const float sc = 1.0f / 128.0f;
    float2* Z = Rs + wrp * 128;      // line buffer alias (Rs dead during inverse)

    for (int yt = 0; yt < 4; yt++) {
        const int y0 = yt * 16;
        __syncthreads();             // protect Rs/Gs from previous phase
        // stage Rs: rows rr=0..37 <-> global y = y0 + rr - 11
        for (int i = tid; i < 9880; i += 512) {
            int u  = i / 2470;
            int rem = i - u * 2470;
            int rr = rem / 65;
            int ff = rem - rr * 65;
            int y  = y0 + rr - 11;
            float2 val = make_float2(0.f, 0.f);
            if (y >= 0 && y < 64)
                val = g_Rhat[(((size_t)bdv * 4 + u) * 64 + y) * 65 + ff];
            Rs[i] = val;
        }
        __syncthreads();

        // ---- mix: f = 0..63, thread: 8y x 4k ----
        {
            float2 acc[8][4];
#pragma unroll
            for (int i = 0; i < 8; i++)
#pragma unroll
                for (int j = 0; j < 4; j++) acc[i][j] = make_float2(0.f, 0.f);

#pragma unroll 1
            for (int u = 0; u < 4; u++) {
                const float2* rbase = Rs + (u * 38 + yh * 8) * 65 + f;
                const float2* w0p = g_What2 + ((size_t)((kq * 4 + 0) * 4 + u) * 23) * WSTRIDE + f;
                const float2* w1p = g_What2 + ((size_t)((kq * 4 + 1) * 4 + u) * 23) * WSTRIDE + f;
                const float2* w2p = g_What2 + ((size_t)((kq * 4 + 2) * 4 + u) * 23) * WSTRIDE + f;
                const float2* w3p = g_What2 + ((size_t)((kq * 4 + 3) * 4 + u) * 23) * WSTRIDE + f;
#pragma unroll 2
                for (int dy = 0; dy < 23; dy++) {
                    float2 w0 = w0p[dy * WSTRIDE];
                    float2 w1 = w1p[dy * WSTRIDE];
                    float2 w2 = w2p[dy * WSTRIDE];
                    float2 w3 = w3p[dy * WSTRIDE];
                    const float2* rptr = rbase + dy * 65;
#pragma unroll
                    for (int i = 0; i < 8; i++) {
                        float2 r = rptr[i * 65];
                        acc[i][0].x = fmaf(r.x, w0.x, acc[i][0].x);
                        acc[i][0].x = fmaf(-r.y, w0.y, acc[i][0].x);
                        acc[i][0].y = fmaf(r.x, w0.y, acc[i][0].y);
                        acc[i][0].y = fmaf(r.y, w0.x, acc[i][0].y);
                        acc[i][1].x = fmaf(r.x, w1.x, acc[i][1].x);
                        acc[i][1].x = fmaf(-r.y, w1.y, acc[i][1].x);
                        acc[i][1].y = fmaf(r.x, w1.y, acc[i][1].y);
                        acc[i][1].y = fmaf(r.y, w1.x, acc[i][1].y);
                        acc[i][2].x = fmaf(r.x, w2.x, acc[i][2].x);
                        acc[i][2].x = fmaf(-r.y, w2.y, acc[i][2].x);
                        acc[i][2].y = fmaf(r.x, w2.y, acc[i][2].y);
                        acc[i][2].y = fmaf(r.y, w2.x, acc[i][2].y);
                        acc[i][3].x = fmaf(r.x, w3.x, acc[i][3].x);
                        acc[i][3].x = fmaf(-r.y, w3.y, acc[i][3].x);
                        acc[i][3].y = fmaf(r.x, w3.y, acc[i][3].y);
                        acc[i][3].y = fmaf(r.y, w3.x, acc[i][3].y);
                    }
                }
            }
            // write to Gs
#pragma unroll
            for (int i = 0; i < 8; i++)
#pragma unroll
                for (int j = 0; j < 4; j++)
                    Gs[((yh * 8 + i) * 16 + kq * 4 + j) * 65 + f] = acc[i][j];
        }

        // ---- f = 64 bin (threads 0..255, one (y,k) cell each) ----
        if (tid < 256) {
            float2 a = make_float2(0.f, 0.f);
#pragma unroll 1
            for (int u = 0; u < 4; u++) {
                const float2* rptr = Rs + (u * 38 + c_y) * 65 + 64;
                const float2* wp = g_What2 + ((size_t)(c_k * 4 + u) * 23) * WSTRIDE + 64;
#pragma unroll
                for (int dy = 0; dy < 23; dy++) {
                    float2 r = rptr[dy * 65];
                    float2 w = wp[dy * WSTRIDE];
                    a.x = fmaf(r.x, w.x, a.x); a.x = fmaf(-r.y, w.y, a.x);
                    a.y = fmaf(r.x, w.y, a.y); a.y = fmaf(r.y, w.x, a.y);
                }
            }
            Gs[(c_y * 16 + c_k) * 65 + 64] = a;
        }
        __syncthreads();   // Gs complete; Rs free for line buffers

        // ---- inverse: warp = (k-pair, y-half), 8 lines each ----
        for (int l = 0; l < 8; l++) {
            const int yl = ihalf * 8 + l;
            const float2* G0 = Gs + (yl * 16 + k0) * 65;
            const float2* G1 = Gs + (yl * 16 + k1) * 65;
#pragma unroll
            for (int t = 0; t < 4; t++) {
                int ff = lane + t * 32;
                float2 z;
                if (ff <= 64) {
                    float2 a = G0[ff], c = G1[ff];
                    z = make_float2(a.x - c.y, a.y + c.x);
                } else {
                    int g = 128 - ff;
                    float2 a = G0[g], c = G1[g];
                    z = make_float2(a.x + c.y, -a.y + c.x);
                }
                Z[ff] = make_float2(z.x, -z.y);
            }
            warp_fft128(Z, lane);
            const int yg = y0 + yl;
            float* d0 = g_Lp + (((size_t)(b * 16 + k0) * 64 + dv)) * N_ + yg * 64;
            float* d1 = g_Lp + (((size_t)(b * 16 + k1) * 64 + dv)) * N_ + yg * 64;
#pragma unroll
            for (int t = 0; t < 2; t++) {
                int x = lane + t * 32;
                float2 o = Z[x];
                d0[x] = o.x * sc + bp0;
                d1[x] = -o.y * sc + bp1;
            }
        }
    }
}

// ---------------------------------------------------------------------------
// K6: final combine
// ---------------------------------------------------------------------------
__global__ __launch_bounds__(128) void final_kernel(float* __restrict__ out) {
    __shared__ float qs[64][128];
    __shared__ float lps[16][128];
    __shared__ float lcs[16][64];
    const int n0 = blockIdx.x * 128;
    const int b  = blockIdx.y;
    const int tid = threadIdx.x;

    const float* qbase = g_proj + (size_t)b * 384 * N_ + n0;
    for (int l = 0; l < 64; l++) {
        int e = tid + l * 128;
        qs[e >> 7][e & 127] = qbase[(size_t)(e >> 7) * N_ + (e & 127)];
    }
#pragma unroll
    for (int l = 0; l < 8; l++) {
        int e = tid + l * 128;
        lcs[e >> 6][e & 63] = g_Lc[b * 1024 + e];
    }

    for (int dv = 0; dv < 64; dv++) {
        __syncthreads();
#pragma unroll
        for (int l = 0; l < 16; l++) {
            int e = tid + l * 128;
            int k = e >> 7, n = e & 127;
            lps[k][n] = g_Lp[(((size_t)b * 16 + k) * 64 + dv) * N_ + n0 + n];
        }
        __syncthreads();
        const int px = tid;
#pragma unroll
        for (int h = 0; h < 4; h++) {
            float y = 0.f;
#pragma unroll
            for (int k = 0; k < 16; k++)
                y = fmaf(qs[h * 16 + k][px], lcs[k][dv] + lps[k][px], y);
            out[((size_t)b * 256 + h * 64 + dv) * N_ + n0 + px] = y;
        }
    }
}

// ---------------------------------------------------------------------------
extern "C" void kernel_launch(void* const* d_in, const int* in_sizes, int n_in,
                              void* d_out, int out_size) {
    const float* x     = (const float*)d_in[0];
    const float* w_q   = (const float*)d_in[1];
    const float* w_k   = (const float*)d_in[2];
    const float* w_v   = (const float*)d_in[3];
    const float* gq    = (const float*)d_in[4];
    const float* bq    = (const float*)d_in[5];
    const float* mq    = (const float*)d_in[6];
    const float* vq    = (const float*)d_in[7];
    const float* gv    = (const float*)d_in[8];
    const float* bv    = (const float*)d_in[9];
    const float* mv    = (const float*)d_in[10];
    const float* vvar  = (const float*)d_in[11];
    const float* w_pos = (const float*)d_in[12];
    const float* b_pos = (const float*)d_in[13];
    float* out = (float*)d_out;

    const int FUSED_SMEM = (16640 + 9880) * sizeof(float2);   // 212,160 B
    cudaFuncSetAttribute(f2f3_fused_kernel,
                         cudaFuncAttributeMaxDynamicSharedMemorySize, FUSED_SMEM);

    twiddle_kernel<<<1, 64>>>();
    fold_kernel<<<2, 256>>>(w_q, w_k, w_v, gq, bq, mq, vq, gv, bv, mv, vvar);
    proj_gemm_kernel<<<dim3(32, 6, 16), 256>>>(x);
    softmax_kernel<<<1024, 256>>>();
    lc_partial_kernel<<<dim3(8, 4, 16), 256>>>();
    lc_reduce_kernel<<<16, 1024>>>();
    what_kernel<<<184, 256>>>(w_pos);
    rhat_kernel<<<32768, 256>>>();
    f2f3_fused_kernel<<<dim3(64, 16), 512, FUSED_SMEM>>>(b_pos);
    final_kernel<<<dim3(32, 16), 128>>>(out);
}